// round 10
// baseline (speedup 1.0000x reference)
#include <cuda_runtime.h>
#include <cstdint>

#define N_NODES 100000
#define N_EDGES 600000
#define IN_DIM  6
#define HID     128
#define EPS     1e-5f
#define SCAN_B  1024
#define SCAN_NB ((N_NODES + SCAN_B - 1) / SCAN_B)   // 98

// ---------------- scratch (device globals: allocation-free) ----------------
__device__ __align__(16) int   g_degi[N_NODES];           // int degree counts
__device__ __align__(16) int   g_off[N_NODES + 1];        // CSR offsets (exclusive)
__device__ __align__(16) int   g_cur[N_NODES];            // scatter cursors
__device__ __align__(16) int   g_esrc[N_EDGES];           // src ids grouped by dst
__device__ __align__(16) int   g_bsum[SCAN_NB];           // scan block sums
__device__ __align__(16) float g_inv[N_NODES];            // 1/max(deg,1)
__device__ __align__(16) float g_agg0[N_NODES * IN_DIM];  // layer-0 neighbor MEAN (6-dim)
__device__ __align__(16) float g_h0[N_NODES * HID];       // layer-0 out (RAW, pre-BN)
__device__ __align__(16) float g_agg1[N_NODES * HID];     // layer-1 neighbor MEAN (activated)
__device__ __align__(16) float g_h1[N_NODES * HID];       // layer-1 out (RAW, pre-BN)
__device__ __align__(16) float g_sum[HID];                // BN partial sums
__device__ __align__(16) float g_sq[HID];
__device__ __align__(16) float g_scale[HID];              // BN affine
__device__ __align__(16) float g_shift[HID];
__device__ __align__(16) float g_pl[N_NODES];             // layer-2 projections
__device__ __align__(16) float g_pr[N_NODES];

// ---------------- zeroing (kernels only) ----------------
__global__ void k_zero() {
    int i = blockIdx.x * blockDim.x + threadIdx.x;
    int stride = gridDim.x * blockDim.x;
    for (int j = i; j < N_NODES; j += stride) { g_degi[j] = 0; g_cur[j] = 0; }
    if (i < HID) { g_sum[i] = 0.0f; g_sq[i] = 0.0f; }
}

__global__ void k_zero_bn() {
    g_sum[threadIdx.x] = 0.0f;
    g_sq[threadIdx.x] = 0.0f;
}

// ---------------- CSR build ----------------
__global__ void k_count(const int* __restrict__ ei) {
    int e = blockIdx.x * blockDim.x + threadIdx.x;
    if (e < N_EDGES) atomicAdd(&g_degi[ei[N_EDGES + e]], 1);
}

__global__ void k_scan1() {
    __shared__ int s[SCAN_B];
    int tid = threadIdx.x;
    int i = blockIdx.x * SCAN_B + tid;
    int v = (i < N_NODES) ? g_degi[i] : 0;
    s[tid] = v;
    __syncthreads();
#pragma unroll
    for (int o = 1; o < SCAN_B; o <<= 1) {
        int t = (tid >= o) ? s[tid - o] : 0;
        __syncthreads();
        s[tid] += t;
        __syncthreads();
    }
    if (i < N_NODES) g_off[i + 1] = s[tid];
    if (tid == SCAN_B - 1) g_bsum[blockIdx.x] = s[tid];
}

// warp exclusive scan over SCAN_NB block sums (4 elems / lane)
__global__ void k_scan2() {
    int lane = threadIdx.x;
    int base = lane * 4;
    int v[4];
#pragma unroll
    for (int q = 0; q < 4; q++) v[q] = (base + q < SCAN_NB) ? g_bsum[base + q] : 0;
    int tot = v[0] + v[1] + v[2] + v[3];
    int inc = tot;
#pragma unroll
    for (int o = 1; o < 32; o <<= 1) {
        int t = __shfl_up_sync(0xffffffffu, inc, o);
        if (lane >= o) inc += t;
    }
    int run = inc - tot;    // exclusive prefix of this lane's chunk
#pragma unroll
    for (int q = 0; q < 4; q++) {
        if (base + q < SCAN_NB) g_bsum[base + q] = run;
        run += v[q];
    }
}

__global__ void k_scan3() {
    int i = blockIdx.x * SCAN_B + threadIdx.x;
    if (i < N_NODES) g_off[i + 1] += g_bsum[blockIdx.x];
    if (i == 0) g_off[0] = 0;
}

__global__ void k_fill(const int* __restrict__ ei) {
    int e = blockIdx.x * blockDim.x + threadIdx.x;
    if (e >= N_EDGES) return;
    int s = ei[e];
    int d = ei[N_EDGES + e];
    int pos = g_off[d] + atomicAdd(&g_cur[d], 1);
    g_esrc[pos] = s;
}

__global__ void k_inv() {
    int n = blockIdx.x * blockDim.x + threadIdx.x;
    if (n < N_NODES) g_inv[n] = 1.0f / fmaxf((float)g_degi[n], 1.0f);
}

// ---------------- layer-0 aggregation (mean, 6-dim, CSR) ----------------
__global__ void k_agg0(const float* __restrict__ x) {
    int n = blockIdx.x * blockDim.x + threadIdx.x;
    if (n >= N_NODES) return;
    int beg = g_off[n], end = g_off[n + 1];
    float a[IN_DIM] = {0.f, 0.f, 0.f, 0.f, 0.f, 0.f};
    for (int j = beg; j < end; j++) {
        int s = g_esrc[j];
        const float* xs = x + s * IN_DIM;
#pragma unroll
        for (int k = 0; k < IN_DIM; k++) a[k] += xs[k];
    }
    float iv = g_inv[n];
#pragma unroll
    for (int k = 0; k < IN_DIM; k++) g_agg0[n * IN_DIM + k] = a[k] * iv;
}

// ---------------- layer-0 conv + fused BN stats ----------------
// h0 = mean0 @ wl.T + bl + x @ wr.T; thread tid owns channel tid.
__global__ void k_layer0(const float* __restrict__ x,
                         const float* __restrict__ wl, const float* __restrict__ bl,
                         const float* __restrict__ wr) {
    __shared__ float sIn[32 * 12];   // per node: [mean6 | x6]
    int n0 = blockIdx.x * 32;
    int tid = threadIdx.x;

    float wlr[IN_DIM], wrr[IN_DIM];
#pragma unroll
    for (int k = 0; k < IN_DIM; k++) {
        wlr[k] = __ldg(&wl[tid * IN_DIM + k]);
        wrr[k] = __ldg(&wr[tid * IN_DIM + k]);
    }
    float bias = __ldg(&bl[tid]);

#pragma unroll
    for (int it = 0; it < 3; it++) {
        int i = tid + it * 128;          // 0..383
        int n = n0 + i / 12, f = i % 12;
        float v = 0.0f;
        if (n < N_NODES) {
            if (f < 6) v = g_agg0[n * IN_DIM + f];
            else       v = x[n * IN_DIM + (f - 6)];
        }
        sIn[i] = v;
    }
    __syncthreads();

    float s = 0.0f, s2 = 0.0f;
    for (int i = 0; i < 32; i++) {
        int n = n0 + i;
        if (n >= N_NODES) break;
        const float* in = &sIn[i * 12];
        float h = bias;
#pragma unroll
        for (int k = 0; k < IN_DIM; k++) h += wlr[k] * in[k] + wrr[k] * in[6 + k];
        g_h0[n * HID + tid] = h;
        s += h; s2 += h * h;
    }
    atomicAdd(&g_sum[tid], s);
    atomicAdd(&g_sq[tid], s2);
}

__global__ void k_bnfinal(const float* __restrict__ gamma, const float* __restrict__ beta) {
    int c = threadIdx.x;
    float mu  = g_sum[c] * (1.0f / N_NODES);
    float var = g_sq[c] * (1.0f / N_NODES) - mu * mu;
    float sc  = gamma[c] * rsqrtf(var + EPS);
    g_scale[c] = sc;
    g_shift[c] = beta[c] - mu * sc;
}

// ---------------- layer-1 aggregation (mean of activated h0, CSR) ----------------
// BN+ReLU applied on load; one warp per node, float4 lane.
__global__ void k_agg1() {
    int w = (blockIdx.x * blockDim.x + threadIdx.x) >> 5;
    if (w >= N_NODES) return;
    int lane = threadIdx.x & 31;
    float4 sc = ((const float4*)g_scale)[lane];
    float4 sh = ((const float4*)g_shift)[lane];
    int beg = __ldg(&g_off[w]), end = __ldg(&g_off[w + 1]);
    float4 acc = make_float4(0.f, 0.f, 0.f, 0.f);
    for (int j = beg; j < end; j++) {
        int s = __ldg(&g_esrc[j]);                 // broadcast load
        float4 v = ((const float4*)(g_h0 + s * HID))[lane];
        acc.x += fmaxf(fmaf(v.x, sc.x, sh.x), 0.0f);
        acc.y += fmaxf(fmaf(v.y, sc.y, sh.y), 0.0f);
        acc.z += fmaxf(fmaf(v.z, sc.z, sh.z), 0.0f);
        acc.w += fmaxf(fmaf(v.w, sc.w, sh.w), 0.0f);
    }
    float iv = g_inv[w];
    acc.x *= iv; acc.y *= iv; acc.z *= iv; acc.w *= iv;
    ((float4*)(g_agg1 + w * HID))[lane] = acc;
}

// ---------------- layer-1 GEMM (tf32 mma.sync) + fused BN(apply h0) + BN stats ----------------
__device__ __forceinline__ uint32_t f2tf32(float f) {
    uint32_t u;
    asm("cvt.rna.tf32.f32 %0, %1;" : "=r"(u) : "f"(f));
    return u;
}

__device__ __forceinline__ void mma_tf32(float& c0, float& c1, float& c2, float& c3,
                                         uint32_t a0, uint32_t a1, uint32_t a2, uint32_t a3,
                                         uint32_t b0, uint32_t b1) {
    asm volatile(
        "mma.sync.aligned.m16n8k8.row.col.f32.tf32.tf32.f32 "
        "{%0,%1,%2,%3}, {%4,%5,%6,%7}, {%8,%9}, {%0,%1,%2,%3};"
        : "+f"(c0), "+f"(c1), "+f"(c2), "+f"(c3)
        : "r"(a0), "r"(a1), "r"(a2), "r"(a3), "r"(b0), "r"(b1));
}

#define ASTR 20   // row stride (floats); 20 => conflict-free fragment LDS

__global__ void __launch_bounds__(256) k_gemm1_tc(const float* __restrict__ wl,
                                                  const float* __restrict__ bl,
                                                  const float* __restrict__ wr) {
    __shared__ float As[64 * ASTR];    // A tile, [m][k], tf32 bits
    __shared__ float Ws[128 * ASTR];   // W tile, [n][k]
    __shared__ float sScale[HID], sShift[HID];

    int tid  = threadIdx.x;
    int n0   = blockIdx.x * 64;
    int warp = tid >> 5, lane = tid & 31;
    int wm = (warp & 1) * 32;          // warp m-offset (0/32)
    int wn = (warp >> 1) * 32;         // warp n-offset (0/32/64/96)
    int gi = lane >> 2, ti = lane & 3; // fragment group/thread ids

    if (tid < HID) { sScale[tid] = g_scale[tid]; sShift[tid] = g_shift[tid]; }

    float c[2][4][4];
#pragma unroll
    for (int i = 0; i < 2; i++)
#pragma unroll
        for (int j = 0; j < 4; j++)
#pragma unroll
            for (int q = 0; q < 4; q++) c[i][j][q] = 0.0f;

    int am = tid >> 2, ak = (tid & 3) * 4;     // A: node row, k4 chunk
    int wc = tid >> 1, wk = (tid & 1) * 8;     // W: channel row, k8 chunk
    int anode = n0 + am;

#pragma unroll 1
    for (int p = 0; p < 2; p++) {
        const float* A = p ? g_h0 : g_agg1;
        const float* W = p ? wr : wl;
#pragma unroll 1
        for (int kt = 0; kt < HID; kt += 16) {
            __syncthreads();
            // A tile 64x16 (p==1: apply layer-0 BN+ReLU on load)
            {
                float4 v = make_float4(0.f, 0.f, 0.f, 0.f);
                if (anode < N_NODES) v = *(const float4*)(A + anode * HID + kt + ak);
                if (p == 1) {
                    float4 sc = *(const float4*)&sScale[kt + ak];
                    float4 sh = *(const float4*)&sShift[kt + ak];
                    v.x = fmaxf(fmaf(v.x, sc.x, sh.x), 0.0f);
                    v.y = fmaxf(fmaf(v.y, sc.y, sh.y), 0.0f);
                    v.z = fmaxf(fmaf(v.z, sc.z, sh.z), 0.0f);
                    v.w = fmaxf(fmaf(v.w, sc.w, sh.w), 0.0f);
                }
                float4 t;
                t.x = __uint_as_float(f2tf32(v.x));
                t.y = __uint_as_float(f2tf32(v.y));
                t.z = __uint_as_float(f2tf32(v.z));
                t.w = __uint_as_float(f2tf32(v.w));
                *(float4*)&As[am * ASTR + ak] = t;
            }
            // W tile 128x16
            {
                const float4* wp = (const float4*)(W + wc * HID + kt + wk);
                float4 w0 = __ldg(wp), w1 = __ldg(wp + 1);
                float4 t0, t1;
                t0.x = __uint_as_float(f2tf32(w0.x));
                t0.y = __uint_as_float(f2tf32(w0.y));
                t0.z = __uint_as_float(f2tf32(w0.z));
                t0.w = __uint_as_float(f2tf32(w0.w));
                t1.x = __uint_as_float(f2tf32(w1.x));
                t1.y = __uint_as_float(f2tf32(w1.y));
                t1.z = __uint_as_float(f2tf32(w1.z));
                t1.w = __uint_as_float(f2tf32(w1.w));
                *(float4*)&Ws[wc * ASTR + wk]     = t0;
                *(float4*)&Ws[wc * ASTR + wk + 4] = t1;
            }
            __syncthreads();

#pragma unroll
            for (int kk = 0; kk < 16; kk += 8) {
                uint32_t a[2][4], b[4][2];
#pragma unroll
                for (int i = 0; i < 2; i++) {
                    int mb = wm + i * 16;
                    a[i][0] = __float_as_uint(As[(mb + gi)     * ASTR + kk + ti]);
                    a[i][1] = __float_as_uint(As[(mb + 8 + gi) * ASTR + kk + ti]);
                    a[i][2] = __float_as_uint(As[(mb + gi)     * ASTR + kk + 4 + ti]);
                    a[i][3] = __float_as_uint(As[(mb + 8 + gi) * ASTR + kk + 4 + ti]);
                }
#pragma unroll
                for (int j = 0; j < 4; j++) {
                    int nb = wn + j * 8;
                    b[j][0] = __float_as_uint(Ws[(nb + gi) * ASTR + kk + ti]);
                    b[j][1] = __float_as_uint(Ws[(nb + gi) * ASTR + kk + 4 + ti]);
                }
#pragma unroll
                for (int i = 0; i < 2; i++)
#pragma unroll
                    for (int j = 0; j < 4; j++)
                        mma_tf32(c[i][j][0], c[i][j][1], c[i][j][2], c[i][j][3],
                                 a[i][0], a[i][1], a[i][2], a[i][3],
                                 b[j][0], b[j][1]);
            }
        }
    }

    // epilogue: + bias, store raw h1, accumulate BN stats per channel
    float ssum[4][2], ssq[4][2];
#pragma unroll
    for (int j = 0; j < 4; j++) { ssum[j][0] = ssum[j][1] = 0.f; ssq[j][0] = ssq[j][1] = 0.f; }

#pragma unroll
    for (int i = 0; i < 2; i++) {
#pragma unroll
        for (int j = 0; j < 4; j++) {
            int ch = wn + j * 8 + ti * 2;
            float b0 = __ldg(&bl[ch]), b1 = __ldg(&bl[ch + 1]);
            int nodeA = n0 + wm + i * 16 + gi;
            int nodeB = nodeA + 8;
            if (nodeA < N_NODES) {
                float o0 = c[i][j][0] + b0, o1 = c[i][j][1] + b1;
                *(float2*)(g_h1 + nodeA * HID + ch) = make_float2(o0, o1);
                ssum[j][0] += o0; ssq[j][0] += o0 * o0;
                ssum[j][1] += o1; ssq[j][1] += o1 * o1;
            }
            if (nodeB < N_NODES) {
                float o2 = c[i][j][2] + b0, o3 = c[i][j][3] + b1;
                *(float2*)(g_h1 + nodeB * HID + ch) = make_float2(o2, o3);
                ssum[j][0] += o2; ssq[j][0] += o2 * o2;
                ssum[j][1] += o3; ssq[j][1] += o3 * o3;
            }
        }
    }
    // reduce across gi lanes (stride-4 butterfly), lanes gi==0 commit
#pragma unroll
    for (int j = 0; j < 4; j++) {
#pragma unroll
        for (int h = 0; h < 2; h++) {
            float a = ssum[j][h], b = ssq[j][h];
#pragma unroll
            for (int o = 4; o < 32; o <<= 1) {
                a += __shfl_xor_sync(0xffffffffu, a, o);
                b += __shfl_xor_sync(0xffffffffu, b, o);
            }
            if (gi == 0) {
                int ch = wn + j * 8 + ti * 2 + h;
                atomicAdd(&g_sum[ch], a);
                atomicAdd(&g_sq[ch], b);
            }
        }
    }
}

// ---------------- layer-2: BN+ReLU on load, project to scalars ----------------
__global__ void k_proj2(const float* __restrict__ wl2, const float* __restrict__ wr2) {
    int gt = blockIdx.x * blockDim.x + threadIdx.x;
    int n = gt >> 5;
    if (n >= N_NODES) return;
    int lane = threadIdx.x & 31;
    float4 sc = ((const float4*)g_scale)[lane];
    float4 sh = ((const float4*)g_shift)[lane];
    float4 h = ((const float4*)(g_h1 + n * HID))[lane];
    h.x = fmaxf(fmaf(h.x, sc.x, sh.x), 0.0f);
    h.y = fmaxf(fmaf(h.y, sc.y, sh.y), 0.0f);
    h.z = fmaxf(fmaf(h.z, sc.z, sh.z), 0.0f);
    h.w = fmaxf(fmaf(h.w, sc.w, sh.w), 0.0f);
    float4 a = __ldg((const float4*)wl2 + lane);
    float4 b = __ldg((const float4*)wr2 + lane);
    float pl = h.x * a.x + h.y * a.y + h.z * a.z + h.w * a.w;
    float pr = h.x * b.x + h.y * b.y + h.z * b.z + h.w * b.w;
#pragma unroll
    for (int o = 16; o > 0; o >>= 1) {
        pl += __shfl_xor_sync(0xffffffffu, pl, o);
        pr += __shfl_xor_sync(0xffffffffu, pr, o);
    }
    if (lane == 0) { g_pl[n] = pl; g_pr[n] = pr; }
}

__global__ void k_final(const float* __restrict__ bl2, float* __restrict__ out) {
    int n = blockIdx.x * blockDim.x + threadIdx.x;
    if (n >= N_NODES) return;
    int beg = g_off[n], end = g_off[n + 1];
    float a = 0.0f;
    for (int j = beg; j < end; j++) a += g_pl[g_esrc[j]];
    float z = a * g_inv[n] + __ldg(bl2) + g_pr[n];
    out[n] = 1.0f / (1.0f + expf(-z));
}

// ---------------- launch: kernel launches ONLY ----------------
extern "C" void kernel_launch(void* const* d_in, const int* in_sizes, int n_in,
                              void* d_out, int out_size) {
    const float* x   = (const float*)d_in[0];
    const int*   ei  = (const int*)d_in[1];   // int32 (JAX x64-disabled demotes int64)
    const float* wl0 = (const float*)d_in[2];
    const float* bl0 = (const float*)d_in[3];
    const float* wr0 = (const float*)d_in[4];
    const float* g0  = (const float*)d_in[5];
    const float* b0  = (const float*)d_in[6];
    const float* wl1 = (const float*)d_in[7];
    const float* bl1 = (const float*)d_in[8];
    const float* wr1 = (const float*)d_in[9];
    const float* g1  = (const float*)d_in[10];
    const float* b1  = (const float*)d_in[11];
    const float* wl2 = (const float*)d_in[12];
    const float* bl2 = (const float*)d_in[13];
    const float* wr2 = (const float*)d_in[14];
    float* out = (float*)d_out;

    k_zero <<<512, 256>>>();

    // CSR build
    k_count<<<(N_EDGES + 255) / 256, 256>>>(ei);
    k_scan1<<<SCAN_NB, SCAN_B>>>();
    k_scan2<<<1, 32>>>();
    k_scan3<<<SCAN_NB, SCAN_B>>>();
    k_fill <<<(N_EDGES + 255) / 256, 256>>>(ei);
    k_inv  <<<(N_NODES + 255) / 256, 256>>>();

    // layer 0 (stats fused into layer0)
    k_agg0  <<<(N_NODES + 255) / 256, 256>>>(x);
    k_layer0<<<(N_NODES + 31) / 32, 128>>>(x, wl0, bl0, wr0);
    k_bnfinal<<<1, 128>>>(g0, b0);

    // layer 1 (BN0 applied on load; stats1 fused into gemm epilogue)
    k_agg1 <<<(N_NODES * 32 + 255) / 256, 256>>>();
    k_zero_bn<<<1, 128>>>();
    k_gemm1_tc<<<(N_NODES + 63) / 64, 256>>>(wl1, bl1, wr1);
    k_bnfinal<<<1, 128>>>(g1, b1);

    // layer 2 (BN1 applied on load)
    k_proj2<<<(N_NODES * 32 + 255) / 256, 256>>>(wl2, wr2);
    k_final<<<(N_NODES + 255) / 256, 256>>>(bl2, out);
}

// round 11
// speedup vs baseline: 1.3736x; 1.3736x over previous
#include <cuda_runtime.h>
#include <cstdint>

#define N_NODES 100000
#define N_EDGES 600000
#define IN_DIM  6
#define HID     128
#define EPS     1e-5f
#define SCAN_B  1024
#define SCAN_NB ((N_NODES + SCAN_B - 1) / SCAN_B)   // 98
#define STAT_NODES 256                              // nodes per bnstats block

// ---------------- scratch (device globals: allocation-free) ----------------
__device__ __align__(16) int   g_degi[N_NODES];           // int degree counts
__device__ __align__(16) int   g_off[N_NODES + 1];        // CSR offsets (exclusive)
__device__ __align__(16) int   g_cur[N_NODES];            // scatter cursors
__device__ __align__(16) int   g_esrc[N_EDGES];           // src ids grouped by dst
__device__ __align__(16) int   g_bsum[SCAN_NB];           // scan block sums
__device__ __align__(16) float g_inv[N_NODES];            // 1/max(deg,1)
__device__ __align__(16) float g_agg0[N_NODES * IN_DIM];  // layer-0 neighbor MEAN (6-dim)
__device__ __align__(16) float g_h0[N_NODES * HID];       // layer-0 out (RAW, pre-BN)
__device__ __align__(16) float g_agg1[N_NODES * HID];     // layer-1 neighbor MEAN (activated)
__device__ __align__(16) float g_h1[N_NODES * HID];       // layer-1 out (RAW, pre-BN)
__device__ __align__(16) float g_sum[HID];                // BN partial sums
__device__ __align__(16) float g_sq[HID];
__device__ __align__(16) float g_scale[HID];              // BN affine
__device__ __align__(16) float g_shift[HID];
__device__ __align__(16) float g_pl[N_NODES];             // layer-2 projections
__device__ __align__(16) float g_pr[N_NODES];

// ---------------- zeroing (kernels only) ----------------
__global__ void k_zero() {
    int i = blockIdx.x * blockDim.x + threadIdx.x;
    int stride = gridDim.x * blockDim.x;
    for (int j = i; j < N_NODES; j += stride) { g_degi[j] = 0; g_cur[j] = 0; }
    if (i < HID) { g_sum[i] = 0.0f; g_sq[i] = 0.0f; }
}

__global__ void k_zero_bn() {
    g_sum[threadIdx.x] = 0.0f;
    g_sq[threadIdx.x] = 0.0f;
}

// ---------------- CSR build ----------------
__global__ void k_count(const int* __restrict__ ei) {
    int e = blockIdx.x * blockDim.x + threadIdx.x;
    if (e < N_EDGES) atomicAdd(&g_degi[ei[N_EDGES + e]], 1);
}

__global__ void k_scan1() {
    __shared__ int s[SCAN_B];
    int tid = threadIdx.x;
    int i = blockIdx.x * SCAN_B + tid;
    int v = (i < N_NODES) ? g_degi[i] : 0;
    s[tid] = v;
    __syncthreads();
#pragma unroll
    for (int o = 1; o < SCAN_B; o <<= 1) {
        int t = (tid >= o) ? s[tid - o] : 0;
        __syncthreads();
        s[tid] += t;
        __syncthreads();
    }
    if (i < N_NODES) g_off[i + 1] = s[tid];
    if (tid == SCAN_B - 1) g_bsum[blockIdx.x] = s[tid];
}

// warp exclusive scan over SCAN_NB block sums (4 elems / lane)
__global__ void k_scan2() {
    int lane = threadIdx.x;
    int base = lane * 4;
    int v[4];
#pragma unroll
    for (int q = 0; q < 4; q++) v[q] = (base + q < SCAN_NB) ? g_bsum[base + q] : 0;
    int tot = v[0] + v[1] + v[2] + v[3];
    int inc = tot;
#pragma unroll
    for (int o = 1; o < 32; o <<= 1) {
        int t = __shfl_up_sync(0xffffffffu, inc, o);
        if (lane >= o) inc += t;
    }
    int run = inc - tot;    // exclusive prefix of this lane's chunk
#pragma unroll
    for (int q = 0; q < 4; q++) {
        if (base + q < SCAN_NB) g_bsum[base + q] = run;
        run += v[q];
    }
}

__global__ void k_scan3() {
    int i = blockIdx.x * SCAN_B + threadIdx.x;
    if (i < N_NODES) g_off[i + 1] += g_bsum[blockIdx.x];
    if (i == 0) g_off[0] = 0;
}

__global__ void k_fill(const int* __restrict__ ei) {
    int e = blockIdx.x * blockDim.x + threadIdx.x;
    if (e >= N_EDGES) return;
    int s = ei[e];
    int d = ei[N_EDGES + e];
    int pos = g_off[d] + atomicAdd(&g_cur[d], 1);
    g_esrc[pos] = s;
}

__global__ void k_inv() {
    int n = blockIdx.x * blockDim.x + threadIdx.x;
    if (n < N_NODES) g_inv[n] = 1.0f / fmaxf((float)g_degi[n], 1.0f);
}

// ---------------- layer-0 aggregation (mean, 6-dim, CSR) ----------------
__global__ void k_agg0(const float* __restrict__ x) {
    int n = blockIdx.x * blockDim.x + threadIdx.x;
    if (n >= N_NODES) return;
    int beg = g_off[n], end = g_off[n + 1];
    float a[IN_DIM] = {0.f, 0.f, 0.f, 0.f, 0.f, 0.f};
    for (int j = beg; j < end; j++) {
        int s = g_esrc[j];
        const float* xs = x + s * IN_DIM;
#pragma unroll
        for (int k = 0; k < IN_DIM; k++) a[k] += xs[k];
    }
    float iv = g_inv[n];
#pragma unroll
    for (int k = 0; k < IN_DIM; k++) g_agg0[n * IN_DIM + k] = a[k] * iv;
}

// ---------------- layer-0 conv: h0 = mean0 @ wl.T + bl + x @ wr.T ----------------
__global__ void k_layer0(const float* __restrict__ x,
                         const float* __restrict__ wl, const float* __restrict__ bl,
                         const float* __restrict__ wr) {
    __shared__ float sIn[32 * 12];   // per node: [mean6 | x6]
    int n0 = blockIdx.x * 32;
    int tid = threadIdx.x;

    float wlr[IN_DIM], wrr[IN_DIM];
#pragma unroll
    for (int k = 0; k < IN_DIM; k++) {
        wlr[k] = __ldg(&wl[tid * IN_DIM + k]);
        wrr[k] = __ldg(&wr[tid * IN_DIM + k]);
    }
    float bias = __ldg(&bl[tid]);

#pragma unroll
    for (int it = 0; it < 3; it++) {
        int i = tid + it * 128;          // 0..383
        int n = n0 + i / 12, f = i % 12;
        float v = 0.0f;
        if (n < N_NODES) {
            if (f < 6) v = g_agg0[n * IN_DIM + f];
            else       v = x[n * IN_DIM + (f - 6)];
        }
        sIn[i] = v;
    }
    __syncthreads();

    for (int i = 0; i < 32; i++) {
        int n = n0 + i;
        if (n >= N_NODES) break;
        const float* in = &sIn[i * 12];
        float h = bias;
#pragma unroll
        for (int k = 0; k < IN_DIM; k++) h += wlr[k] * in[k] + wrr[k] * in[6 + k];
        g_h0[n * HID + tid] = h;
    }
}

// ---------------- BN stats: 256 nodes per block -> 391-long atomic chains ----------------
__device__ __forceinline__ void bnstats_body(const float* h) {
    int c = threadIdx.x;
    int n0 = blockIdx.x * STAT_NODES;
    float s = 0.0f, s2 = 0.0f;
    for (int i = 0; i < STAT_NODES; i++) {
        int n = n0 + i;
        if (n >= N_NODES) break;
        float v = h[n * HID + c];
        s += v; s2 += v * v;
    }
    atomicAdd(&g_sum[c], s);
    atomicAdd(&g_sq[c], s2);
}
__global__ void k_bnstats0() { bnstats_body(g_h0); }
__global__ void k_bnstats1() { bnstats_body(g_h1); }

__global__ void k_bnfinal(const float* __restrict__ gamma, const float* __restrict__ beta) {
    int c = threadIdx.x;
    float mu  = g_sum[c] * (1.0f / N_NODES);
    float var = g_sq[c] * (1.0f / N_NODES) - mu * mu;
    float sc  = gamma[c] * rsqrtf(var + EPS);
    g_scale[c] = sc;
    g_shift[c] = beta[c] - mu * sc;
}

// ---------------- layer-1 aggregation (mean of activated h0, CSR) ----------------
// BN+ReLU applied on load; one warp per node, float4 lane.
__global__ void k_agg1() {
    int w = (blockIdx.x * blockDim.x + threadIdx.x) >> 5;
    if (w >= N_NODES) return;
    int lane = threadIdx.x & 31;
    float4 sc = ((const float4*)g_scale)[lane];
    float4 sh = ((const float4*)g_shift)[lane];
    int beg = __ldg(&g_off[w]), end = __ldg(&g_off[w + 1]);
    float4 acc = make_float4(0.f, 0.f, 0.f, 0.f);
    for (int j = beg; j < end; j++) {
        int s = __ldg(&g_esrc[j]);                 // broadcast load
        float4 v = ((const float4*)(g_h0 + s * HID))[lane];
        acc.x += fmaxf(fmaf(v.x, sc.x, sh.x), 0.0f);
        acc.y += fmaxf(fmaf(v.y, sc.y, sh.y), 0.0f);
        acc.z += fmaxf(fmaf(v.z, sc.z, sh.z), 0.0f);
        acc.w += fmaxf(fmaf(v.w, sc.w, sh.w), 0.0f);
    }
    float iv = g_inv[w];
    acc.x *= iv; acc.y *= iv; acc.z *= iv; acc.w *= iv;
    ((float4*)(g_agg1 + w * HID))[lane] = acc;
}

// ---------------- layer-1 GEMM (tf32 mma.sync), BN(h0) applied on load ----------------
__device__ __forceinline__ uint32_t f2tf32(float f) {
    uint32_t u;
    asm("cvt.rna.tf32.f32 %0, %1;" : "=r"(u) : "f"(f));
    return u;
}

__device__ __forceinline__ void mma_tf32(float& c0, float& c1, float& c2, float& c3,
                                         uint32_t a0, uint32_t a1, uint32_t a2, uint32_t a3,
                                         uint32_t b0, uint32_t b1) {
    asm volatile(
        "mma.sync.aligned.m16n8k8.row.col.f32.tf32.tf32.f32 "
        "{%0,%1,%2,%3}, {%4,%5,%6,%7}, {%8,%9}, {%0,%1,%2,%3};"
        : "+f"(c0), "+f"(c1), "+f"(c2), "+f"(c3)
        : "r"(a0), "r"(a1), "r"(a2), "r"(a3), "r"(b0), "r"(b1));
}

#define ASTR 20   // row stride (floats); 20 => conflict-free fragment LDS

__global__ void __launch_bounds__(256) k_gemm1_tc(const float* __restrict__ wl,
                                                  const float* __restrict__ bl,
                                                  const float* __restrict__ wr) {
    __shared__ float As[64 * ASTR];    // A tile, [m][k], tf32 bits
    __shared__ float Ws[128 * ASTR];   // W tile, [n][k]
    __shared__ float sScale[HID], sShift[HID];

    int tid  = threadIdx.x;
    int n0   = blockIdx.x * 64;
    int warp = tid >> 5, lane = tid & 31;
    int wm = (warp & 1) * 32;          // warp m-offset (0/32)
    int wn = (warp >> 1) * 32;         // warp n-offset (0/32/64/96)
    int gi = lane >> 2, ti = lane & 3; // fragment group/thread ids

    if (tid < HID) { sScale[tid] = g_scale[tid]; sShift[tid] = g_shift[tid]; }

    float c[2][4][4];
#pragma unroll
    for (int i = 0; i < 2; i++)
#pragma unroll
        for (int j = 0; j < 4; j++)
#pragma unroll
            for (int q = 0; q < 4; q++) c[i][j][q] = 0.0f;

    int am = tid >> 2, ak = (tid & 3) * 4;     // A: node row, k4 chunk
    int wc = tid >> 1, wk = (tid & 1) * 8;     // W: channel row, k8 chunk
    int anode = n0 + am;

#pragma unroll 1
    for (int p = 0; p < 2; p++) {
        const float* A = p ? g_h0 : g_agg1;
        const float* W = p ? wr : wl;
#pragma unroll 1
        for (int kt = 0; kt < HID; kt += 16) {
            __syncthreads();
            // A tile 64x16 (p==1: apply layer-0 BN+ReLU on load)
            {
                float4 v = make_float4(0.f, 0.f, 0.f, 0.f);
                if (anode < N_NODES) v = *(const float4*)(A + anode * HID + kt + ak);
                if (p == 1) {
                    float4 sc = *(const float4*)&sScale[kt + ak];
                    float4 sh = *(const float4*)&sShift[kt + ak];
                    v.x = fmaxf(fmaf(v.x, sc.x, sh.x), 0.0f);
                    v.y = fmaxf(fmaf(v.y, sc.y, sh.y), 0.0f);
                    v.z = fmaxf(fmaf(v.z, sc.z, sh.z), 0.0f);
                    v.w = fmaxf(fmaf(v.w, sc.w, sh.w), 0.0f);
                }
                float4 t;
                t.x = __uint_as_float(f2tf32(v.x));
                t.y = __uint_as_float(f2tf32(v.y));
                t.z = __uint_as_float(f2tf32(v.z));
                t.w = __uint_as_float(f2tf32(v.w));
                *(float4*)&As[am * ASTR + ak] = t;
            }
            // W tile 128x16
            {
                const float4* wp = (const float4*)(W + wc * HID + kt + wk);
                float4 w0 = __ldg(wp), w1 = __ldg(wp + 1);
                float4 t0, t1;
                t0.x = __uint_as_float(f2tf32(w0.x));
                t0.y = __uint_as_float(f2tf32(w0.y));
                t0.z = __uint_as_float(f2tf32(w0.z));
                t0.w = __uint_as_float(f2tf32(w0.w));
                t1.x = __uint_as_float(f2tf32(w1.x));
                t1.y = __uint_as_float(f2tf32(w1.y));
                t1.z = __uint_as_float(f2tf32(w1.z));
                t1.w = __uint_as_float(f2tf32(w1.w));
                *(float4*)&Ws[wc * ASTR + wk]     = t0;
                *(float4*)&Ws[wc * ASTR + wk + 4] = t1;
            }
            __syncthreads();

#pragma unroll
            for (int kk = 0; kk < 16; kk += 8) {
                uint32_t a[2][4], b[4][2];
#pragma unroll
                for (int i = 0; i < 2; i++) {
                    int mb = wm + i * 16;
                    a[i][0] = __float_as_uint(As[(mb + gi)     * ASTR + kk + ti]);
                    a[i][1] = __float_as_uint(As[(mb + 8 + gi) * ASTR + kk + ti]);
                    a[i][2] = __float_as_uint(As[(mb + gi)     * ASTR + kk + 4 + ti]);
                    a[i][3] = __float_as_uint(As[(mb + 8 + gi) * ASTR + kk + 4 + ti]);
                }
#pragma unroll
                for (int j = 0; j < 4; j++) {
                    int nb = wn + j * 8;
                    b[j][0] = __float_as_uint(Ws[(nb + gi) * ASTR + kk + ti]);
                    b[j][1] = __float_as_uint(Ws[(nb + gi) * ASTR + kk + 4 + ti]);
                }
#pragma unroll
                for (int i = 0; i < 2; i++)
#pragma unroll
                    for (int j = 0; j < 4; j++)
                        mma_tf32(c[i][j][0], c[i][j][1], c[i][j][2], c[i][j][3],
                                 a[i][0], a[i][1], a[i][2], a[i][3],
                                 b[j][0], b[j][1]);
            }
        }
    }

    // epilogue: + bias, store raw h1
#pragma unroll
    for (int i = 0; i < 2; i++) {
#pragma unroll
        for (int j = 0; j < 4; j++) {
            int ch = wn + j * 8 + ti * 2;
            float b0 = __ldg(&bl[ch]), b1 = __ldg(&bl[ch + 1]);
            int nodeA = n0 + wm + i * 16 + gi;
            int nodeB = nodeA + 8;
            if (nodeA < N_NODES) {
                float2 o = make_float2(c[i][j][0] + b0, c[i][j][1] + b1);
                *(float2*)(g_h1 + nodeA * HID + ch) = o;
            }
            if (nodeB < N_NODES) {
                float2 o = make_float2(c[i][j][2] + b0, c[i][j][3] + b1);
                *(float2*)(g_h1 + nodeB * HID + ch) = o;
            }
        }
    }
}

// ---------------- layer-2: BN+ReLU on load, project to scalars ----------------
__global__ void k_proj2(const float* __restrict__ wl2, const float* __restrict__ wr2) {
    int gt = blockIdx.x * blockDim.x + threadIdx.x;
    int n = gt >> 5;
    if (n >= N_NODES) return;
    int lane = threadIdx.x & 31;
    float4 sc = ((const float4*)g_scale)[lane];
    float4 sh = ((const float4*)g_shift)[lane];
    float4 h = ((const float4*)(g_h1 + n * HID))[lane];
    h.x = fmaxf(fmaf(h.x, sc.x, sh.x), 0.0f);
    h.y = fmaxf(fmaf(h.y, sc.y, sh.y), 0.0f);
    h.z = fmaxf(fmaf(h.z, sc.z, sh.z), 0.0f);
    h.w = fmaxf(fmaf(h.w, sc.w, sh.w), 0.0f);
    float4 a = __ldg((const float4*)wl2 + lane);
    float4 b = __ldg((const float4*)wr2 + lane);
    float pl = h.x * a.x + h.y * a.y + h.z * a.z + h.w * a.w;
    float pr = h.x * b.x + h.y * b.y + h.z * b.z + h.w * b.w;
#pragma unroll
    for (int o = 16; o > 0; o >>= 1) {
        pl += __shfl_xor_sync(0xffffffffu, pl, o);
        pr += __shfl_xor_sync(0xffffffffu, pr, o);
    }
    if (lane == 0) { g_pl[n] = pl; g_pr[n] = pr; }
}

__global__ void k_final(const float* __restrict__ bl2, float* __restrict__ out) {
    int n = blockIdx.x * blockDim.x + threadIdx.x;
    if (n >= N_NODES) return;
    int beg = g_off[n], end = g_off[n + 1];
    float a = 0.0f;
    for (int j = beg; j < end; j++) a += g_pl[g_esrc[j]];
    float z = a * g_inv[n] + __ldg(bl2) + g_pr[n];
    out[n] = 1.0f / (1.0f + expf(-z));
}

// ---------------- launch: kernel launches ONLY ----------------
extern "C" void kernel_launch(void* const* d_in, const int* in_sizes, int n_in,
                              void* d_out, int out_size) {
    const float* x   = (const float*)d_in[0];
    const int*   ei  = (const int*)d_in[1];   // int32 (JAX x64-disabled demotes int64)
    const float* wl0 = (const float*)d_in[2];
    const float* bl0 = (const float*)d_in[3];
    const float* wr0 = (const float*)d_in[4];
    const float* g0  = (const float*)d_in[5];
    const float* b0  = (const float*)d_in[6];
    const float* wl1 = (const float*)d_in[7];
    const float* bl1 = (const float*)d_in[8];
    const float* wr1 = (const float*)d_in[9];
    const float* g1  = (const float*)d_in[10];
    const float* b1  = (const float*)d_in[11];
    const float* wl2 = (const float*)d_in[12];
    const float* bl2 = (const float*)d_in[13];
    const float* wr2 = (const float*)d_in[14];
    float* out = (float*)d_out;

    k_zero <<<512, 256>>>();

    // CSR build
    k_count<<<(N_EDGES + 255) / 256, 256>>>(ei);
    k_scan1<<<SCAN_NB, SCAN_B>>>();
    k_scan2<<<1, 32>>>();
    k_scan3<<<SCAN_NB, SCAN_B>>>();
    k_fill <<<(N_EDGES + 255) / 256, 256>>>(ei);
    k_inv  <<<(N_NODES + 255) / 256, 256>>>();

    // layer 0
    k_agg0  <<<(N_NODES + 255) / 256, 256>>>(x);
    k_layer0<<<(N_NODES + 31) / 32, 128>>>(x, wl0, bl0, wr0);
    k_bnstats0<<<(N_NODES + STAT_NODES - 1) / STAT_NODES, 128>>>();
    k_bnfinal <<<1, 128>>>(g0, b0);

    // layer 1 (BN0 applied on load in agg1 + gemm)
    k_agg1 <<<(N_NODES * 32 + 255) / 256, 256>>>();
    k_gemm1_tc<<<(N_NODES + 63) / 64, 256>>>(wl1, bl1, wr1);
    k_zero_bn <<<1, 128>>>();
    k_bnstats1<<<(N_NODES + STAT_NODES - 1) / STAT_NODES, 128>>>();
    k_bnfinal <<<1, 128>>>(g1, b1);

    // layer 2 (BN1 applied on load)
    k_proj2<<<(N_NODES * 32 + 255) / 256, 256>>>(wl2, wr2);
    k_final<<<(N_NODES + 255) / 256, 256>>>(bl2, out);
}

// round 12
// speedup vs baseline: 1.4196x; 1.0335x over previous
#include <cuda_runtime.h>
#include <cstdint>

#define N_NODES 100000
#define N_EDGES 600000
#define IN_DIM  6
#define HID     128
#define EPS     1e-5f
#define SCAN_B  1024
#define SCAN_NB ((N_NODES + SCAN_B - 1) / SCAN_B)   // 98
#define L0_BLOCKS ((N_NODES + 31) / 32)             // 3125
#define GM_BLOCKS ((N_NODES + 63) / 64)             // 1563

// ---------------- scratch (device globals: allocation-free) ----------------
__device__ __align__(16) int    g_degi[N_NODES];           // int degree counts
__device__ __align__(16) int    g_off[N_NODES + 1];        // CSR offsets (exclusive)
__device__ __align__(16) int    g_cur[N_NODES];            // scatter cursors
__device__ __align__(16) int    g_esrc[N_EDGES];           // src ids grouped by dst
__device__ __align__(16) int    g_bsum[SCAN_NB];           // scan block sums
__device__ __align__(16) float  g_inv[N_NODES];            // 1/max(deg,1)
__device__ __align__(16) float  g_agg0[N_NODES * IN_DIM];  // layer-0 neighbor MEAN
__device__ __align__(16) float  g_h0[N_NODES * HID];       // layer-0 out (RAW)
__device__ __align__(16) float  g_agg1[N_NODES * HID];     // layer-1 neighbor MEAN (activated)
__device__ __align__(16) float  g_h1[N_NODES * HID];       // layer-1 out (RAW)
__device__ __align__(16) float2 g_p0[L0_BLOCKS * HID];     // layer-0 stats partials (s, s2)
__device__ __align__(16) float2 g_p1[GM_BLOCKS * 2 * HID]; // layer-1 stats partials
__device__ __align__(16) float  g_sum0[HID], g_sq0[HID];   // BN0 totals
__device__ __align__(16) float  g_sum1[HID], g_sq1[HID];   // BN1 totals
__device__ __align__(16) float  g_pl[N_NODES];             // layer-2 projections
__device__ __align__(16) float  g_pr[N_NODES];

// ---------------- BN affine helper (from raw stats) ----------------
__device__ __forceinline__ void bn_affine(float s, float q, float gam, float bet,
                                          float& sc, float& sh) {
    float mu  = s * (1.0f / N_NODES);
    float var = q * (1.0f / N_NODES) - mu * mu;
    sc = gam * rsqrtf(var + EPS);
    sh = bet - mu * sc;
}

// ---------------- zeroing (kernels only) ----------------
__global__ void k_zero() {
    int i = blockIdx.x * blockDim.x + threadIdx.x;
    int stride = gridDim.x * blockDim.x;
    for (int j = i; j < N_NODES; j += stride) { g_degi[j] = 0; g_cur[j] = 0; }
    if (i < HID) { g_sum0[i] = 0.0f; g_sq0[i] = 0.0f; g_sum1[i] = 0.0f; g_sq1[i] = 0.0f; }
}

// ---------------- CSR build ----------------
__global__ void k_count(const int* __restrict__ ei) {
    int e = blockIdx.x * blockDim.x + threadIdx.x;
    if (e < N_EDGES) atomicAdd(&g_degi[ei[N_EDGES + e]], 1);
}

__global__ void k_scan1() {
    __shared__ int s[SCAN_B];
    int tid = threadIdx.x;
    int i = blockIdx.x * SCAN_B + tid;
    int v = (i < N_NODES) ? g_degi[i] : 0;
    s[tid] = v;
    __syncthreads();
#pragma unroll
    for (int o = 1; o < SCAN_B; o <<= 1) {
        int t = (tid >= o) ? s[tid - o] : 0;
        __syncthreads();
        s[tid] += t;
        __syncthreads();
    }
    if (i < N_NODES) g_off[i + 1] = s[tid];
    if (tid == SCAN_B - 1) g_bsum[blockIdx.x] = s[tid];
}

__global__ void k_scan2() {
    int lane = threadIdx.x;
    int base = lane * 4;
    int v[4];
#pragma unroll
    for (int q = 0; q < 4; q++) v[q] = (base + q < SCAN_NB) ? g_bsum[base + q] : 0;
    int tot = v[0] + v[1] + v[2] + v[3];
    int inc = tot;
#pragma unroll
    for (int o = 1; o < 32; o <<= 1) {
        int t = __shfl_up_sync(0xffffffffu, inc, o);
        if (lane >= o) inc += t;
    }
    int run = inc - tot;
#pragma unroll
    for (int q = 0; q < 4; q++) {
        if (base + q < SCAN_NB) g_bsum[base + q] = run;
        run += v[q];
    }
}

// scan3 + inv fused (g_degi is final after k_count)
__global__ void k_scan3i() {
    int i = blockIdx.x * SCAN_B + threadIdx.x;
    if (i < N_NODES) {
        g_off[i + 1] += g_bsum[blockIdx.x];
        g_inv[i] = 1.0f / fmaxf((float)g_degi[i], 1.0f);
    }
    if (i == 0) g_off[0] = 0;
}

__global__ void k_fill(const int* __restrict__ ei) {
    int e = blockIdx.x * blockDim.x + threadIdx.x;
    if (e >= N_EDGES) return;
    int s = ei[e];
    int d = ei[N_EDGES + e];
    int pos = g_off[d] + atomicAdd(&g_cur[d], 1);
    g_esrc[pos] = s;
}

// ---------------- layer-0 aggregation (mean, 6-dim, CSR) ----------------
__global__ void k_agg0(const float* __restrict__ x) {
    int n = blockIdx.x * blockDim.x + threadIdx.x;
    if (n >= N_NODES) return;
    int beg = g_off[n], end = g_off[n + 1];
    float a[IN_DIM] = {0.f, 0.f, 0.f, 0.f, 0.f, 0.f};
    for (int j = beg; j < end; j++) {
        int s = g_esrc[j];
        const float* xs = x + s * IN_DIM;
#pragma unroll
        for (int k = 0; k < IN_DIM; k++) a[k] += xs[k];
    }
    float iv = g_inv[n];
#pragma unroll
    for (int k = 0; k < IN_DIM; k++) g_agg0[n * IN_DIM + k] = a[k] * iv;
}

// ---------------- layer-0 conv + stats partials (no atomics) ----------------
__global__ void k_layer0(const float* __restrict__ x,
                         const float* __restrict__ wl, const float* __restrict__ bl,
                         const float* __restrict__ wr) {
    __shared__ float sIn[32 * 12];   // per node: [mean6 | x6]
    int n0 = blockIdx.x * 32;
    int tid = threadIdx.x;

    float wlr[IN_DIM], wrr[IN_DIM];
#pragma unroll
    for (int k = 0; k < IN_DIM; k++) {
        wlr[k] = __ldg(&wl[tid * IN_DIM + k]);
        wrr[k] = __ldg(&wr[tid * IN_DIM + k]);
    }
    float bias = __ldg(&bl[tid]);

#pragma unroll
    for (int it = 0; it < 3; it++) {
        int i = tid + it * 128;          // 0..383
        int n = n0 + i / 12, f = i % 12;
        float v = 0.0f;
        if (n < N_NODES) {
            if (f < 6) v = g_agg0[n * IN_DIM + f];
            else       v = x[n * IN_DIM + (f - 6)];
        }
        sIn[i] = v;
    }
    __syncthreads();

    float s = 0.0f, s2 = 0.0f;
    for (int i = 0; i < 32; i++) {
        int n = n0 + i;
        if (n >= N_NODES) break;
        const float* in = &sIn[i * 12];
        float h = bias;
#pragma unroll
        for (int k = 0; k < IN_DIM; k++) h += wlr[k] * in[k] + wrr[k] * in[6 + k];
        g_h0[n * HID + tid] = h;
        s += h; s2 += h * h;
    }
    g_p0[blockIdx.x * HID + tid] = make_float2(s, s2);   // plain store, no atomics
}

// ---------------- stats reduction: 32 blocks, 32-long atomic chains ----------------
__global__ void k_reduce0() {
    int c = threadIdx.x;
    float s = 0.0f, q = 0.0f;
    for (int b = blockIdx.x; b < L0_BLOCKS; b += 32) {
        float2 v = g_p0[b * HID + c];
        s += v.x; q += v.y;
    }
    atomicAdd(&g_sum0[c], s);
    atomicAdd(&g_sq0[c], q);
}

__global__ void k_reduce1() {
    int c = threadIdx.x;
    float s = 0.0f, q = 0.0f;
    for (int b = blockIdx.x; b < GM_BLOCKS * 2; b += 32) {
        float2 v = g_p1[b * HID + c];
        s += v.x; q += v.y;
    }
    atomicAdd(&g_sum1[c], s);
    atomicAdd(&g_sq1[c], q);
}

// ---------------- layer-1 aggregation (mean of activated h0, CSR) ----------------
// BN0 affine computed inline per lane from raw stats.
__global__ void k_agg1(const float* __restrict__ g0, const float* __restrict__ b0) {
    int w = (blockIdx.x * blockDim.x + threadIdx.x) >> 5;
    if (w >= N_NODES) return;
    int lane = threadIdx.x & 31;
    float4 s4 = ((const float4*)g_sum0)[lane];
    float4 q4 = ((const float4*)g_sq0)[lane];
    float4 gm = __ldg((const float4*)g0 + lane);
    float4 bt = __ldg((const float4*)b0 + lane);
    float4 sc, sh;
    bn_affine(s4.x, q4.x, gm.x, bt.x, sc.x, sh.x);
    bn_affine(s4.y, q4.y, gm.y, bt.y, sc.y, sh.y);
    bn_affine(s4.z, q4.z, gm.z, bt.z, sc.z, sh.z);
    bn_affine(s4.w, q4.w, gm.w, bt.w, sc.w, sh.w);

    int beg = __ldg(&g_off[w]), end = __ldg(&g_off[w + 1]);
    float4 acc = make_float4(0.f, 0.f, 0.f, 0.f);
    for (int j = beg; j < end; j++) {
        int s = __ldg(&g_esrc[j]);                 // broadcast load
        float4 v = ((const float4*)(g_h0 + s * HID))[lane];
        acc.x += fmaxf(fmaf(v.x, sc.x, sh.x), 0.0f);
        acc.y += fmaxf(fmaf(v.y, sc.y, sh.y), 0.0f);
        acc.z += fmaxf(fmaf(v.z, sc.z, sh.z), 0.0f);
        acc.w += fmaxf(fmaf(v.w, sc.w, sh.w), 0.0f);
    }
    float iv = g_inv[w];
    acc.x *= iv; acc.y *= iv; acc.z *= iv; acc.w *= iv;
    ((float4*)(g_agg1 + w * HID))[lane] = acc;
}

// ---------------- layer-1 GEMM (tf32 mma.sync, K-tile 32) ----------------
__device__ __forceinline__ uint32_t f2tf32(float f) {
    uint32_t u;
    asm("cvt.rna.tf32.f32 %0, %1;" : "=r"(u) : "f"(f));
    return u;
}

__device__ __forceinline__ void mma_tf32(float& c0, float& c1, float& c2, float& c3,
                                         uint32_t a0, uint32_t a1, uint32_t a2, uint32_t a3,
                                         uint32_t b0, uint32_t b1) {
    asm volatile(
        "mma.sync.aligned.m16n8k8.row.col.f32.tf32.tf32.f32 "
        "{%0,%1,%2,%3}, {%4,%5,%6,%7}, {%8,%9}, {%0,%1,%2,%3};"
        : "+f"(c0), "+f"(c1), "+f"(c2), "+f"(c3)
        : "r"(a0), "r"(a1), "r"(a2), "r"(a3), "r"(b0), "r"(b1));
}

#define ASTR 36   // row stride (floats) for K=32 tiles; (4*gi+ti) mod 32 unique -> conflict-free frags

__global__ void __launch_bounds__(256) k_gemm1_tc(const float* __restrict__ wl,
                                                  const float* __restrict__ bl,
                                                  const float* __restrict__ wr,
                                                  const float* __restrict__ g0,
                                                  const float* __restrict__ b0) {
    __shared__ float As[64 * ASTR];    // 9.2 KB
    __shared__ float Ws[128 * ASTR];   // 18.4 KB
    __shared__ float sScale[HID], sShift[HID];

    int tid  = threadIdx.x;
    int n0   = blockIdx.x * 64;
    int warp = tid >> 5, lane = tid & 31;
    int wm = (warp & 1) * 32;          // warp m-offset (0/32)
    int wn = (warp >> 1) * 32;         // warp n-offset (0/32/64/96)
    int gi = lane >> 2, ti = lane & 3;

    if (tid < HID) {
        float sc, sh;
        bn_affine(g_sum0[tid], g_sq0[tid], __ldg(&g0[tid]), __ldg(&b0[tid]), sc, sh);
        sScale[tid] = sc; sShift[tid] = sh;
    }

    float c[2][4][4];
#pragma unroll
    for (int i = 0; i < 2; i++)
#pragma unroll
        for (int j = 0; j < 4; j++)
#pragma unroll
            for (int q = 0; q < 4; q++) c[i][j][q] = 0.0f;

    int am = tid >> 2, ak = (tid & 3) * 8;     // A: row 0..63, col chunk 0/8/16/24
    int wc = tid >> 1, wk = (tid & 1) * 16;    // W: row 0..127, col chunk 0/16
    int anode = n0 + am;

#pragma unroll 1
    for (int p = 0; p < 2; p++) {
        const float* A = p ? g_h0 : g_agg1;
        const float* W = p ? wr : wl;
#pragma unroll 1
        for (int kt = 0; kt < HID; kt += 32) {
            __syncthreads();
            // A tile 64x32 (p==1: BN0+ReLU on load)
            {
                float4 v0 = make_float4(0.f, 0.f, 0.f, 0.f), v1 = v0;
                if (anode < N_NODES) {
                    const float4* ap = (const float4*)(A + anode * HID + kt + ak);
                    v0 = ap[0]; v1 = ap[1];
                }
                if (p == 1) {
                    float4 sc0 = *(const float4*)&sScale[kt + ak];
                    float4 sh0 = *(const float4*)&sShift[kt + ak];
                    float4 sc1 = *(const float4*)&sScale[kt + ak + 4];
                    float4 sh1 = *(const float4*)&sShift[kt + ak + 4];
                    v0.x = fmaxf(fmaf(v0.x, sc0.x, sh0.x), 0.0f);
                    v0.y = fmaxf(fmaf(v0.y, sc0.y, sh0.y), 0.0f);
                    v0.z = fmaxf(fmaf(v0.z, sc0.z, sh0.z), 0.0f);
                    v0.w = fmaxf(fmaf(v0.w, sc0.w, sh0.w), 0.0f);
                    v1.x = fmaxf(fmaf(v1.x, sc1.x, sh1.x), 0.0f);
                    v1.y = fmaxf(fmaf(v1.y, sc1.y, sh1.y), 0.0f);
                    v1.z = fmaxf(fmaf(v1.z, sc1.z, sh1.z), 0.0f);
                    v1.w = fmaxf(fmaf(v1.w, sc1.w, sh1.w), 0.0f);
                }
                float4 t0, t1;
                t0.x = __uint_as_float(f2tf32(v0.x));
                t0.y = __uint_as_float(f2tf32(v0.y));
                t0.z = __uint_as_float(f2tf32(v0.z));
                t0.w = __uint_as_float(f2tf32(v0.w));
                t1.x = __uint_as_float(f2tf32(v1.x));
                t1.y = __uint_as_float(f2tf32(v1.y));
                t1.z = __uint_as_float(f2tf32(v1.z));
                t1.w = __uint_as_float(f2tf32(v1.w));
                *(float4*)&As[am * ASTR + ak]     = t0;
                *(float4*)&As[am * ASTR + ak + 4] = t1;
            }
            // W tile 128x32
            {
                const float4* wp = (const float4*)(W + wc * HID + kt + wk);
#pragma unroll
                for (int q = 0; q < 4; q++) {
                    float4 w0 = __ldg(wp + q);
                    float4 t;
                    t.x = __uint_as_float(f2tf32(w0.x));
                    t.y = __uint_as_float(f2tf32(w0.y));
                    t.z = __uint_as_float(f2tf32(w0.z));
                    t.w = __uint_as_float(f2tf32(w0.w));
                    *(float4*)&Ws[wc * ASTR + wk + q * 4] = t;
                }
            }
            __syncthreads();

#pragma unroll
            for (int kk = 0; kk < 32; kk += 8) {
                uint32_t a[2][4], b[4][2];
#pragma unroll
                for (int i = 0; i < 2; i++) {
                    int mb = wm + i * 16;
                    a[i][0] = __float_as_uint(As[(mb + gi)     * ASTR + kk + ti]);
                    a[i][1] = __float_as_uint(As[(mb + 8 + gi) * ASTR + kk + ti]);
                    a[i][2] = __float_as_uint(As[(mb + gi)     * ASTR + kk + 4 + ti]);
                    a[i][3] = __float_as_uint(As[(mb + 8 + gi) * ASTR + kk + 4 + ti]);
                }
#pragma unroll
                for (int j = 0; j < 4; j++) {
                    int nb = wn + j * 8;
                    b[j][0] = __float_as_uint(Ws[(nb + gi) * ASTR + kk + ti]);
                    b[j][1] = __float_as_uint(Ws[(nb + gi) * ASTR + kk + 4 + ti]);
                }
#pragma unroll
                for (int i = 0; i < 2; i++)
#pragma unroll
                    for (int j = 0; j < 4; j++)
                        mma_tf32(c[i][j][0], c[i][j][1], c[i][j][2], c[i][j][3],
                                 a[i][0], a[i][1], a[i][2], a[i][3],
                                 b[j][0], b[j][1]);
            }
        }
    }

    // epilogue: + bias, store raw h1, per-warp stats partials (no atomics)
    float ssum[4][2], ssq[4][2];
#pragma unroll
    for (int j = 0; j < 4; j++) { ssum[j][0] = ssum[j][1] = 0.f; ssq[j][0] = ssq[j][1] = 0.f; }

#pragma unroll
    for (int i = 0; i < 2; i++) {
#pragma unroll
        for (int j = 0; j < 4; j++) {
            int ch = wn + j * 8 + ti * 2;
            float b0v = __ldg(&bl[ch]), b1v = __ldg(&bl[ch + 1]);
            int nodeA = n0 + wm + i * 16 + gi;
            int nodeB = nodeA + 8;
            if (nodeA < N_NODES) {
                float o0 = c[i][j][0] + b0v, o1 = c[i][j][1] + b1v;
                *(float2*)(g_h1 + nodeA * HID + ch) = make_float2(o0, o1);
                ssum[j][0] += o0; ssq[j][0] += o0 * o0;
                ssum[j][1] += o1; ssq[j][1] += o1 * o1;
            }
            if (nodeB < N_NODES) {
                float o2 = c[i][j][2] + b0v, o3 = c[i][j][3] + b1v;
                *(float2*)(g_h1 + nodeB * HID + ch) = make_float2(o2, o3);
                ssum[j][0] += o2; ssq[j][0] += o2 * o2;
                ssum[j][1] += o3; ssq[j][1] += o3 * o3;
            }
        }
    }
    // butterfly over gi lanes; lanes gi==0 store partial (slot = m-half, no races)
    int slot = blockIdx.x * 2 + (warp & 1);
#pragma unroll
    for (int j = 0; j < 4; j++) {
#pragma unroll
        for (int h = 0; h < 2; h++) {
            float a = ssum[j][h], b = ssq[j][h];
#pragma unroll
            for (int o = 4; o < 32; o <<= 1) {
                a += __shfl_xor_sync(0xffffffffu, a, o);
                b += __shfl_xor_sync(0xffffffffu, b, o);
            }
            if (gi == 0) {
                int ch = wn + j * 8 + ti * 2 + h;
                g_p1[slot * HID + ch] = make_float2(a, b);
            }
        }
    }
}

// ---------------- layer-2: BN1+ReLU on load (inline affine), project ----------------
__global__ void k_proj2(const float* __restrict__ wl2, const float* __restrict__ wr2,
                        const float* __restrict__ g1, const float* __restrict__ b1) {
    int gt = blockIdx.x * blockDim.x + threadIdx.x;
    int n = gt >> 5;
    if (n >= N_NODES) return;
    int lane = threadIdx.x & 31;
    float4 s4 = ((const float4*)g_sum1)[lane];
    float4 q4 = ((const float4*)g_sq1)[lane];
    float4 gm = __ldg((const float4*)g1 + lane);
    float4 bt = __ldg((const float4*)b1 + lane);
    float4 sc, sh;
    bn_affine(s4.x, q4.x, gm.x, bt.x, sc.x, sh.x);
    bn_affine(s4.y, q4.y, gm.y, bt.y, sc.y, sh.y);
    bn_affine(s4.z, q4.z, gm.z, bt.z, sc.z, sh.z);
    bn_affine(s4.w, q4.w, gm.w, bt.w, sc.w, sh.w);

    float4 h = ((const float4*)(g_h1 + n * HID))[lane];
    h.x = fmaxf(fmaf(h.x, sc.x, sh.x), 0.0f);
    h.y = fmaxf(fmaf(h.y, sc.y, sh.y), 0.0f);
    h.z = fmaxf(fmaf(h.z, sc.z, sh.z), 0.0f);
    h.w = fmaxf(fmaf(h.w, sc.w, sh.w), 0.0f);
    float4 a = __ldg((const float4*)wl2 + lane);
    float4 b = __ldg((const float4*)wr2 + lane);
    float pl = h.x * a.x + h.y * a.y + h.z * a.z + h.w * a.w;
    float pr = h.x * b.x + h.y * b.y + h.z * b.z + h.w * b.w;
#pragma unroll
    for (int o = 16; o > 0; o >>= 1) {
        pl += __shfl_xor_sync(0xffffffffu, pl, o);
        pr += __shfl_xor_sync(0xffffffffu, pr, o);
    }
    if (lane == 0) { g_pl[n] = pl; g_pr[n] = pr; }
}

__global__ void k_final(const float* __restrict__ bl2, float* __restrict__ out) {
    int n = blockIdx.x * blockDim.x + threadIdx.x;
    if (n >= N_NODES) return;
    int beg = g_off[n], end = g_off[n + 1];
    float a = 0.0f;
    for (int j = beg; j < end; j++) a += g_pl[g_esrc[j]];
    float z = a * g_inv[n] + __ldg(bl2) + g_pr[n];
    out[n] = 1.0f / (1.0f + expf(-z));
}

// ---------------- launch: kernel launches ONLY (14 launches) ----------------
extern "C" void kernel_launch(void* const* d_in, const int* in_sizes, int n_in,
                              void* d_out, int out_size) {
    const float* x   = (const float*)d_in[0];
    const int*   ei  = (const int*)d_in[1];   // int32 (JAX x64-disabled demotes int64)
    const float* wl0 = (const float*)d_in[2];
    const float* bl0 = (const float*)d_in[3];
    const float* wr0 = (const float*)d_in[4];
    const float* g0  = (const float*)d_in[5];
    const float* b0  = (const float*)d_in[6];
    const float* wl1 = (const float*)d_in[7];
    const float* bl1 = (const float*)d_in[8];
    const float* wr1 = (const float*)d_in[9];
    const float* g1  = (const float*)d_in[10];
    const float* b1  = (const float*)d_in[11];
    const float* wl2 = (const float*)d_in[12];
    const float* bl2 = (const float*)d_in[13];
    const float* wr2 = (const float*)d_in[14];
    float* out = (float*)d_out;

    k_zero  <<<512, 256>>>();
    k_count <<<(N_EDGES + 255) / 256, 256>>>(ei);
    k_scan1 <<<SCAN_NB, SCAN_B>>>();
    k_scan2 <<<1, 32>>>();
    k_scan3i<<<SCAN_NB, SCAN_B>>>();
    k_fill  <<<(N_EDGES + 255) / 256, 256>>>(ei);

    k_agg0   <<<(N_NODES + 255) / 256, 256>>>(x);
    k_layer0 <<<L0_BLOCKS, 128>>>(x, wl0, bl0, wr0);
    k_reduce0<<<32, 128>>>();

    k_agg1    <<<(N_NODES * 32 + 255) / 256, 256>>>(g0, b0);
    k_gemm1_tc<<<GM_BLOCKS, 256>>>(wl1, bl1, wr1, g0, b0);
    k_reduce1 <<<32, 128>>>();

    k_proj2<<<(N_NODES * 32 + 255) / 256, 256>>>(wl2, wr2, g1, b1);
    k_final<<<(N_NODES + 255) / 256, 256>>>(bl2, out);
}

// round 16
// speedup vs baseline: 1.5043x; 1.0597x over previous
#include <cuda_runtime.h>
#include <cstdint>

#define N_NODES 100000
#define N_EDGES 600000
#define IN_DIM  6
#define HID     128
#define EPS     1e-5f
#define SCAN_B  1024
#define SCAN_NB ((N_NODES + SCAN_B - 1) / SCAN_B)   // 98
#define L0_BLOCKS ((N_NODES + 31) / 32)             // 3125
#define GM_BLOCKS ((N_NODES + 63) / 64)             // 1563

// ---------------- scratch (device globals: allocation-free) ----------------
__device__ __align__(16) int    g_degi[N_NODES];           // int degree counts
__device__ __align__(16) int    g_off[N_NODES + 1];        // CSR offsets (exclusive)
__device__ __align__(16) int    g_cur[N_NODES];            // scatter cursors
__device__ __align__(16) int    g_esrc[N_EDGES];           // src ids grouped by dst
__device__ __align__(16) int    g_bsum[SCAN_NB];           // scan block sums (raw totals)
__device__ __align__(16) float  g_inv[N_NODES];            // 1/max(deg,1)
__device__ __align__(16) float  g_agg0[N_NODES * IN_DIM];  // layer-0 neighbor MEAN
__device__ __align__(16) float  g_h0[N_NODES * HID];       // layer-0 out (RAW)
__device__ __align__(16) float  g_h1[N_NODES * HID];       // layer-1 out (RAW)
__device__ __align__(16) float2 g_p0[L0_BLOCKS * HID];     // layer-0 stats partials (s, s2)
__device__ __align__(16) float2 g_p1[GM_BLOCKS * 2 * HID]; // layer-1 stats partials
__device__ __align__(16) float  g_sum0[HID], g_sq0[HID];   // BN0 totals
__device__ __align__(16) float  g_sum1[HID], g_sq1[HID];   // BN1 totals
__device__ __align__(16) float  g_pl[N_NODES];             // layer-2 projections
__device__ __align__(16) float  g_pr[N_NODES];

// ---------------- BN affine helper (from raw stats) ----------------
__device__ __forceinline__ void bn_affine(float s, float q, float gam, float bet,
                                          float& sc, float& sh) {
    float mu  = s * (1.0f / N_NODES);
    float var = q * (1.0f / N_NODES) - mu * mu;
    sc = gam * rsqrtf(var + EPS);
    sh = bet - mu * sc;
}

// ---------------- zeroing (kernels only) ----------------
__global__ void k_zero() {
    int i = blockIdx.x * blockDim.x + threadIdx.x;
    int stride = gridDim.x * blockDim.x;
    for (int j = i; j < N_NODES; j += stride) { g_degi[j] = 0; g_cur[j] = 0; }
    if (i < HID) { g_sum0[i] = 0.0f; g_sq0[i] = 0.0f; g_sum1[i] = 0.0f; g_sq1[i] = 0.0f; }
}

// ---------------- CSR build ----------------
__global__ void k_count(const int* __restrict__ ei) {
    int e = blockIdx.x * blockDim.x + threadIdx.x;
    if (e < N_EDGES) atomicAdd(&g_degi[ei[N_EDGES + e]], 1);
}

__global__ void k_scan1() {
    __shared__ int s[SCAN_B];
    int tid = threadIdx.x;
    int i = blockIdx.x * SCAN_B + tid;
    int v = (i < N_NODES) ? g_degi[i] : 0;
    s[tid] = v;
    __syncthreads();
#pragma unroll
    for (int o = 1; o < SCAN_B; o <<= 1) {
        int t = (tid >= o) ? s[tid - o] : 0;
        __syncthreads();
        s[tid] += t;
        __syncthreads();
    }
    if (i < N_NODES) g_off[i + 1] = s[tid];
    if (tid == SCAN_B - 1) g_bsum[blockIdx.x] = s[tid];
}

// scan3 + block-prefix (each block redundantly sums its prefix of g_bsum) + inv
__global__ void k_scan3i() {
    __shared__ int sPre;
    int tid = threadIdx.x;
    if (tid < 32) {
        int s = 0;
        for (int b = tid; b < (int)blockIdx.x; b += 32) s += g_bsum[b];
#pragma unroll
        for (int o = 16; o > 0; o >>= 1) s += __shfl_xor_sync(0xffffffffu, s, o);
        if (tid == 0) sPre = s;
    }
    __syncthreads();
    int i = blockIdx.x * SCAN_B + tid;
    if (i < N_NODES) {
        g_off[i + 1] += sPre;
        g_inv[i] = 1.0f / fmaxf((float)g_degi[i], 1.0f);
    }
    if (i == 0) g_off[0] = 0;
}

__global__ void k_fill(const int* __restrict__ ei) {
    int e = blockIdx.x * blockDim.x + threadIdx.x;
    if (e >= N_EDGES) return;
    int s = ei[e];
    int d = ei[N_EDGES + e];
    int pos = g_off[d] + atomicAdd(&g_cur[d], 1);
    g_esrc[pos] = s;
}

// ---------------- layer-0 aggregation (mean, 6-dim, CSR) ----------------
__global__ void k_agg0(const float* __restrict__ x) {
    int n = blockIdx.x * blockDim.x + threadIdx.x;
    if (n >= N_NODES) return;
    int beg = g_off[n], end = g_off[n + 1];
    float a[IN_DIM] = {0.f, 0.f, 0.f, 0.f, 0.f, 0.f};
    for (int j = beg; j < end; j++) {
        int s = g_esrc[j];
        const float* xs = x + s * IN_DIM;
#pragma unroll
        for (int k = 0; k < IN_DIM; k++) a[k] += xs[k];
    }
    float iv = g_inv[n];
#pragma unroll
    for (int k = 0; k < IN_DIM; k++) g_agg0[n * IN_DIM + k] = a[k] * iv;
}

// ---------------- layer-0 conv + stats partials (no atomics) ----------------
__global__ void k_layer0(const float* __restrict__ x,
                         const float* __restrict__ wl, const float* __restrict__ bl,
                         const float* __restrict__ wr) {
    __shared__ float sIn[32 * 12];   // per node: [mean6 | x6]
    int n0 = blockIdx.x * 32;
    int tid = threadIdx.x;

    float wlr[IN_DIM], wrr[IN_DIM];
#pragma unroll
    for (int k = 0; k < IN_DIM; k++) {
        wlr[k] = __ldg(&wl[tid * IN_DIM + k]);
        wrr[k] = __ldg(&wr[tid * IN_DIM + k]);
    }
    float bias = __ldg(&bl[tid]);

#pragma unroll
    for (int it = 0; it < 3; it++) {
        int i = tid + it * 128;          // 0..383
        int n = n0 + i / 12, f = i % 12;
        float v = 0.0f;
        if (n < N_NODES) {
            if (f < 6) v = g_agg0[n * IN_DIM + f];
            else       v = x[n * IN_DIM + (f - 6)];
        }
        sIn[i] = v;
    }
    __syncthreads();

    float s = 0.0f, s2 = 0.0f;
    for (int i = 0; i < 32; i++) {
        int n = n0 + i;
        if (n >= N_NODES) break;
        const float* in = &sIn[i * 12];
        float h = bias;
#pragma unroll
        for (int k = 0; k < IN_DIM; k++) h += wlr[k] * in[k] + wrr[k] * in[6 + k];
        g_h0[n * HID + tid] = h;
        s += h; s2 += h * h;
    }
    g_p0[blockIdx.x * HID + tid] = make_float2(s, s2);   // plain store, no atomics
}

// ---------------- stats reduction: 32 blocks, 32-long atomic chains ----------------
__global__ void k_reduce0() {
    int c = threadIdx.x;
    float s = 0.0f, q = 0.0f;
    for (int b = blockIdx.x; b < L0_BLOCKS; b += 32) {
        float2 v = g_p0[b * HID + c];
        s += v.x; q += v.y;
    }
    atomicAdd(&g_sum0[c], s);
    atomicAdd(&g_sq0[c], q);
}

__global__ void k_reduce1() {
    int c = threadIdx.x;
    float s = 0.0f, q = 0.0f;
    for (int b = blockIdx.x; b < GM_BLOCKS * 2; b += 32) {
        float2 v = g_p1[b * HID + c];
        s += v.x; q += v.y;
    }
    atomicAdd(&g_sum1[c], s);
    atomicAdd(&g_sq1[c], q);
}

// ---------------- layer-1 fused: CSR gather-mean + GEMM (tf32 mma.sync) ----------------
__device__ __forceinline__ uint32_t f2tf32(float f) {
    uint32_t u;
    asm("cvt.rna.tf32.f32 %0, %1;" : "=r"(u) : "f"(f));
    return u;
}

__device__ __forceinline__ void mma_tf32(float& c0, float& c1, float& c2, float& c3,
                                         uint32_t a0, uint32_t a1, uint32_t a2, uint32_t a3,
                                         uint32_t b0, uint32_t b1) {
    asm volatile(
        "mma.sync.aligned.m16n8k8.row.col.f32.tf32.tf32.f32 "
        "{%0,%1,%2,%3}, {%4,%5,%6,%7}, {%8,%9}, {%0,%1,%2,%3};"
        : "+f"(c0), "+f"(c1), "+f"(c2), "+f"(c3)
        : "r"(a0), "r"(a1), "r"(a2), "r"(a3), "r"(b0), "r"(b1));
}

#define AFSTR 132  // full-width A tile row stride; 132 % 32 == 4 -> frag loads conflict-free
#define WSTR  20   // W tile (k=16) row stride; verified conflict-free fragment reads

__global__ void __launch_bounds__(256) k_gemm1f(const float* __restrict__ wl,
                                                const float* __restrict__ bl,
                                                const float* __restrict__ wr,
                                                const float* __restrict__ g0,
                                                const float* __restrict__ b0) {
    __shared__ float As[64 * AFSTR];   // 33.8 KB — full 64x128 A tile (tf32 bits)
    __shared__ float Ws[128 * WSTR];   // 10.2 KB — 128x16 W tile
    __shared__ float sScale[HID], sShift[HID];

    int tid  = threadIdx.x;
    int n0   = blockIdx.x * 64;
    int warp = tid >> 5, lane = tid & 31;
    int wm = (warp & 1) * 32;          // warp m-offset (0/32)
    int wn = (warp >> 1) * 32;         // warp n-offset (0/32/64/96)
    int gi = lane >> 2, ti = lane & 3;

    if (tid < HID) {
        float sc, sh;
        bn_affine(g_sum0[tid], g_sq0[tid], __ldg(&g0[tid]), __ldg(&b0[tid]), sc, sh);
        sScale[tid] = sc; sShift[tid] = sh;
    }
    __syncthreads();

    // ---- gather phase: neighbor-mean of BN0+ReLU(h0) straight into As (tf32) ----
    {
        float4 sc = *(const float4*)&sScale[lane * 4];
        float4 sh = *(const float4*)&sShift[lane * 4];
        int rbase = warp * 8;
#pragma unroll 1
        for (int r = 0; r < 8; r++) {
            int n = n0 + rbase + r;
            float4 acc = make_float4(0.f, 0.f, 0.f, 0.f);
            if (n < N_NODES) {
                int beg = __ldg(&g_off[n]), end = __ldg(&g_off[n + 1]);
                for (int j = beg; j < end; j++) {
                    int s = __ldg(&g_esrc[j]);     // broadcast
                    float4 v = ((const float4*)(g_h0 + (size_t)s * HID))[lane];
                    acc.x += fmaxf(fmaf(v.x, sc.x, sh.x), 0.0f);
                    acc.y += fmaxf(fmaf(v.y, sc.y, sh.y), 0.0f);
                    acc.z += fmaxf(fmaf(v.z, sc.z, sh.z), 0.0f);
                    acc.w += fmaxf(fmaf(v.w, sc.w, sh.w), 0.0f);
                }
                float iv = __ldg(&g_inv[n]);
                acc.x *= iv; acc.y *= iv; acc.z *= iv; acc.w *= iv;
            }
            float* dst = &As[(rbase + r) * AFSTR + lane * 4];
            dst[0] = __uint_as_float(f2tf32(acc.x));
            dst[1] = __uint_as_float(f2tf32(acc.y));
            dst[2] = __uint_as_float(f2tf32(acc.z));
            dst[3] = __uint_as_float(f2tf32(acc.w));
        }
    }
    __syncthreads();

    float c[2][4][4];
#pragma unroll
    for (int i = 0; i < 2; i++)
#pragma unroll
        for (int j = 0; j < 4; j++)
#pragma unroll
            for (int q = 0; q < 4; q++) c[i][j][q] = 0.0f;

    int wc = tid >> 1, wk = (tid & 1) * 8;   // W staging: row, k8 chunk

#pragma unroll 1
    for (int p = 0; p < 2; p++) {
        const float* W = p ? wr : wl;
        if (p == 1) {
            // restage As with BN0+ReLU(h0) for the root term (prev sync covers reads)
            int r = tid >> 2;
            int anode = n0 + r;
#pragma unroll
            for (int j = 0; j < 8; j++) {
                int col = (tid & 3) * 4 + j * 16;
                float4 v = make_float4(0.f, 0.f, 0.f, 0.f);
                if (anode < N_NODES) v = *(const float4*)(g_h0 + (size_t)anode * HID + col);
                float4 sc = *(const float4*)&sScale[col];
                float4 sh = *(const float4*)&sShift[col];
                v.x = fmaxf(fmaf(v.x, sc.x, sh.x), 0.0f);
                v.y = fmaxf(fmaf(v.y, sc.y, sh.y), 0.0f);
                v.z = fmaxf(fmaf(v.z, sc.z, sh.z), 0.0f);
                v.w = fmaxf(fmaf(v.w, sc.w, sh.w), 0.0f);
                float* dst = &As[r * AFSTR + col];
                dst[0] = __uint_as_float(f2tf32(v.x));
                dst[1] = __uint_as_float(f2tf32(v.y));
                dst[2] = __uint_as_float(f2tf32(v.z));
                dst[3] = __uint_as_float(f2tf32(v.w));
            }
        }
#pragma unroll 1
        for (int kt = 0; kt < HID; kt += 16) {
            // stage W 128x16 (also covers the p==1 As restage on first iter)
            {
                const float4* wp = (const float4*)(W + wc * HID + kt + wk);
                float4 w0 = __ldg(wp), w1 = __ldg(wp + 1);
                float4 t0, t1;
                t0.x = __uint_as_float(f2tf32(w0.x));
                t0.y = __uint_as_float(f2tf32(w0.y));
                t0.z = __uint_as_float(f2tf32(w0.z));
                t0.w = __uint_as_float(f2tf32(w0.w));
                t1.x = __uint_as_float(f2tf32(w1.x));
                t1.y = __uint_as_float(f2tf32(w1.y));
                t1.z = __uint_as_float(f2tf32(w1.z));
                t1.w = __uint_as_float(f2tf32(w1.w));
                *(float4*)&Ws[wc * WSTR + wk]     = t0;
                *(float4*)&Ws[wc * WSTR + wk + 4] = t1;
            }
            __syncthreads();

#pragma unroll
            for (int kk2 = 0; kk2 < 16; kk2 += 8) {
                int kcol = kt + kk2;
                uint32_t a[2][4], b[4][2];
#pragma unroll
                for (int i = 0; i < 2; i++) {
                    int mb = wm + i * 16;
                    a[i][0] = __float_as_uint(As[(mb + gi)     * AFSTR + kcol + ti]);
                    a[i][1] = __float_as_uint(As[(mb + 8 + gi) * AFSTR + kcol + ti]);
                    a[i][2] = __float_as_uint(As[(mb + gi)     * AFSTR + kcol + 4 + ti]);
                    a[i][3] = __float_as_uint(As[(mb + 8 + gi) * AFSTR + kcol + 4 + ti]);
                }
#pragma unroll
                for (int j = 0; j < 4; j++) {
                    int nb = wn + j * 8;
                    b[j][0] = __float_as_uint(Ws[(nb + gi) * WSTR + kk2 + ti]);
                    b[j][1] = __float_as_uint(Ws[(nb + gi) * WSTR + kk2 + 4 + ti]);
                }
#pragma unroll
                for (int i = 0; i < 2; i++)
#pragma unroll
                    for (int j = 0; j < 4; j++)
                        mma_tf32(c[i][j][0], c[i][j][1], c[i][j][2], c[i][j][3],
                                 a[i][0], a[i][1], a[i][2], a[i][3],
                                 b[j][0], b[j][1]);
            }
            __syncthreads();   // protect next stage (W and/or As overwrite)
        }
    }

    // epilogue: + bias, store raw h1, per-warp stats partials (no atomics)
    float ssum[4][2], ssq[4][2];
#pragma unroll
    for (int j = 0; j < 4; j++) { ssum[j][0] = ssum[j][1] = 0.f; ssq[j][0] = ssq[j][1] = 0.f; }

#pragma unroll
    for (int i = 0; i < 2; i++) {
#pragma unroll
        for (int j = 0; j < 4; j++) {
            int ch = wn + j * 8 + ti * 2;
            float b0v = __ldg(&bl[ch]), b1v = __ldg(&bl[ch + 1]);
            int nodeA = n0 + wm + i * 16 + gi;
            int nodeB = nodeA + 8;
            if (nodeA < N_NODES) {
                float o0 = c[i][j][0] + b0v, o1 = c[i][j][1] + b1v;
                *(float2*)(g_h1 + (size_t)nodeA * HID + ch) = make_float2(o0, o1);
                ssum[j][0] += o0; ssq[j][0] += o0 * o0;
                ssum[j][1] += o1; ssq[j][1] += o1 * o1;
            }
            if (nodeB < N_NODES) {
                float o2 = c[i][j][2] + b0v, o3 = c[i][j][3] + b1v;
                *(float2*)(g_h1 + (size_t)nodeB * HID + ch) = make_float2(o2, o3);
                ssum[j][0] += o2; ssq[j][0] += o2 * o2;
                ssum[j][1] += o3; ssq[j][1] += o3 * o3;
            }
        }
    }
    int slot = blockIdx.x * 2 + (warp & 1);
#pragma unroll
    for (int j = 0; j < 4; j++) {
#pragma unroll
        for (int h = 0; h < 2; h++) {
            float a = ssum[j][h], b = ssq[j][h];
#pragma unroll
            for (int o = 4; o < 32; o <<= 1) {
                a += __shfl_xor_sync(0xffffffffu, a, o);
                b += __shfl_xor_sync(0xffffffffu, b, o);
            }
            if (gi == 0) {
                int ch = wn + j * 8 + ti * 2 + h;
                g_p1[slot * HID + ch] = make_float2(a, b);
            }
        }
    }
}

// ---------------- layer-2: BN1+ReLU on load (inline affine), project ----------------
__global__ void k_proj2(const float* __restrict__ wl2, const float* __restrict__ wr2,
                        const float* __restrict__ g1, const float* __restrict__ b1) {
    int gt = blockIdx.x * blockDim.x + threadIdx.x;
    int n = gt >> 5;
    if (n >= N_NODES) return;
    int lane = threadIdx.x & 31;
    float4 s4 = ((const float4*)g_sum1)[lane];
    float4 q4 = ((const float4*)g_sq1)[lane];
    float4 gm = __ldg((const float4*)g1 + lane);
    float4 bt = __ldg((const float4*)b1 + lane);
    float4 sc, sh;
    bn_affine(s4.x, q4.x, gm.x, bt.x, sc.x, sh.x);
    bn_affine(s4.y, q4.y, gm.y, bt.y, sc.y, sh.y);
    bn_affine(s4.z, q4.z, gm.z, bt.z, sc.z, sh.z);
    bn_affine(s4.w, q4.w, gm.w, bt.w, sc.w, sh.w);

    float4 h = ((const float4*)(g_h1 + (size_t)n * HID))[lane];
    h.x = fmaxf(fmaf(h.x, sc.x, sh.x), 0.0f);
    h.y = fmaxf(fmaf(h.y, sc.y, sh.y), 0.0f);
    h.z = fmaxf(fmaf(h.z, sc.z, sh.z), 0.0f);
    h.w = fmaxf(fmaf(h.w, sc.w, sh.w), 0.0f);
    float4 a = __ldg((const float4*)wl2 + lane);
    float4 b = __ldg((const float4*)wr2 + lane);
    float pl = h.x * a.x + h.y * a.y + h.z * a.z + h.w * a.w;
    float pr = h.x * b.x + h.y * b.y + h.z * b.z + h.w * b.w;
#pragma unroll
    for (int o = 16; o > 0; o >>= 1) {
        pl += __shfl_xor_sync(0xffffffffu, pl, o);
        pr += __shfl_xor_sync(0xffffffffu, pr, o);
    }
    if (lane == 0) { g_pl[n] = pl; g_pr[n] = pr; }
}

__global__ void k_final(const float* __restrict__ bl2, float* __restrict__ out) {
    int n = blockIdx.x * blockDim.x + threadIdx.x;
    if (n >= N_NODES) return;
    int beg = g_off[n], end = g_off[n + 1];
    float a = 0.0f;
    for (int j = beg; j < end; j++) a += g_pl[g_esrc[j]];
    float z = a * g_inv[n] + __ldg(bl2) + g_pr[n];
    out[n] = 1.0f / (1.0f + expf(-z));
}

// ---------------- launch: kernel launches ONLY (12 launches) ----------------
extern "C" void kernel_launch(void* const* d_in, const int* in_sizes, int n_in,
                              void* d_out, int out_size) {
    const float* x   = (const float*)d_in[0];
    const int*   ei  = (const int*)d_in[1];   // int32 (JAX x64-disabled demotes int64)
    const float* wl0 = (const float*)d_in[2];
    const float* bl0 = (const float*)d_in[3];
    const float* wr0 = (const float*)d_in[4];
    const float* g0  = (const float*)d_in[5];
    const float* b0  = (const float*)d_in[6];
    const float* wl1 = (const float*)d_in[7];
    const float* bl1 = (const float*)d_in[8];
    const float* wr1 = (const float*)d_in[9];
    const float* g1  = (const float*)d_in[10];
    const float* b1  = (const float*)d_in[11];
    const float* wl2 = (const float*)d_in[12];
    const float* bl2 = (const float*)d_in[13];
    const float* wr2 = (const float*)d_in[14];
    float* out = (float*)d_out;

    k_zero  <<<512, 256>>>();
    k_count <<<(N_EDGES + 255) / 256, 256>>>(ei);
    k_scan1 <<<SCAN_NB, SCAN_B>>>();
    k_scan3i<<<SCAN_NB, SCAN_B>>>();
    k_fill  <<<(N_EDGES + 255) / 256, 256>>>(ei);

    k_agg0   <<<(N_NODES + 255) / 256, 256>>>(x);
    k_layer0 <<<L0_BLOCKS, 128>>>(x, wl0, bl0, wr0);
    k_reduce0<<<32, 128>>>();

    k_gemm1f <<<GM_BLOCKS, 256>>>(wl1, bl1, wr1, g0, b0);
    k_reduce1<<<32, 128>>>();

    k_proj2<<<(N_NODES * 32 + 255) / 256, 256>>>(wl2, wr2, g1, b1);
    k_final<<<(N_NODES + 255) / 256, 256>>>(bl2, out);
}

// round 17
// speedup vs baseline: 1.5827x; 1.0521x over previous
#include <cuda_runtime.h>
#include <cuda_fp16.h>
#include <cstdint>

#define N_NODES 100000
#define N_EDGES 600000
#define IN_DIM  6
#define HID     128
#define EPS     1e-5f
#define SCAN_B  1024
#define SCAN_NB ((N_NODES + SCAN_B - 1) / SCAN_B)   // 98
#define L0_BLOCKS ((N_NODES + 31) / 32)             // 3125
#define GM_BLOCKS ((N_NODES + 63) / 64)             // 1563

// ---------------- scratch (device globals: allocation-free) ----------------
__device__ __align__(16) int    g_degi[N_NODES];           // int degree counts
__device__ __align__(16) int    g_off[N_NODES + 1];        // CSR offsets (exclusive)
__device__ __align__(16) int    g_cur[N_NODES];            // scatter cursors
__device__ __align__(16) int    g_esrc[N_EDGES];           // src ids grouped by dst
__device__ __align__(16) int    g_bsum[SCAN_NB];           // scan block sums (raw totals)
__device__ __align__(16) float  g_inv[N_NODES];            // 1/max(deg,1)
__device__ __align__(16) __half g_h0[N_NODES * HID];       // layer-0 out (RAW, fp16)
__device__ __align__(16) __half g_h1[N_NODES * HID];       // layer-1 out (RAW, fp16)
__device__ __align__(16) float2 g_p0[L0_BLOCKS * HID];     // layer-0 stats partials (s, s2)
__device__ __align__(16) float2 g_p1[GM_BLOCKS * 2 * HID]; // layer-1 stats partials
__device__ __align__(16) float  g_sum0[HID], g_sq0[HID];   // BN0 totals
__device__ __align__(16) float  g_sum1[HID], g_sq1[HID];   // BN1 totals
__device__ __align__(16) float  g_pl[N_NODES];             // layer-2 projections
__device__ __align__(16) float  g_pr[N_NODES];

// ---------------- BN affine helper (from raw stats) ----------------
__device__ __forceinline__ void bn_affine(float s, float q, float gam, float bet,
                                          float& sc, float& sh) {
    float mu  = s * (1.0f / N_NODES);
    float var = q * (1.0f / N_NODES) - mu * mu;
    sc = gam * rsqrtf(var + EPS);
    sh = bet - mu * sc;
}

// ---------------- zeroing (kernels only) ----------------
__global__ void k_zero() {
    int i = blockIdx.x * blockDim.x + threadIdx.x;
    int stride = gridDim.x * blockDim.x;
    for (int j = i; j < N_NODES; j += stride) { g_degi[j] = 0; g_cur[j] = 0; }
    if (i < HID) { g_sum0[i] = 0.0f; g_sq0[i] = 0.0f; g_sum1[i] = 0.0f; g_sq1[i] = 0.0f; }
}

// ---------------- CSR build ----------------
__global__ void k_count(const int* __restrict__ ei) {
    int e = blockIdx.x * blockDim.x + threadIdx.x;
    if (e < N_EDGES) atomicAdd(&g_degi[ei[N_EDGES + e]], 1);
}

__global__ void k_scan1() {
    __shared__ int s[SCAN_B];
    int tid = threadIdx.x;
    int i = blockIdx.x * SCAN_B + tid;
    int v = (i < N_NODES) ? g_degi[i] : 0;
    s[tid] = v;
    __syncthreads();
#pragma unroll
    for (int o = 1; o < SCAN_B; o <<= 1) {
        int t = (tid >= o) ? s[tid - o] : 0;
        __syncthreads();
        s[tid] += t;
        __syncthreads();
    }
    if (i < N_NODES) g_off[i + 1] = s[tid];
    if (tid == SCAN_B - 1) g_bsum[blockIdx.x] = s[tid];
}

// scan3 + block-prefix (each block redundantly sums its prefix of g_bsum) + inv
__global__ void k_scan3i() {
    __shared__ int sPre;
    int tid = threadIdx.x;
    if (tid < 32) {
        int s = 0;
        for (int b = tid; b < (int)blockIdx.x; b += 32) s += g_bsum[b];
#pragma unroll
        for (int o = 16; o > 0; o >>= 1) s += __shfl_xor_sync(0xffffffffu, s, o);
        if (tid == 0) sPre = s;
    }
    __syncthreads();
    int i = blockIdx.x * SCAN_B + tid;
    if (i < N_NODES) {
        g_off[i + 1] += sPre;
        g_inv[i] = 1.0f / fmaxf((float)g_degi[i], 1.0f);
    }
    if (i == 0) g_off[0] = 0;
}

__global__ void k_fill(const int* __restrict__ ei) {
    int e = blockIdx.x * blockDim.x + threadIdx.x;
    if (e >= N_EDGES) return;
    int s = ei[e];
    int d = ei[N_EDGES + e];
    int pos = g_off[d] + atomicAdd(&g_cur[d], 1);
    g_esrc[pos] = s;
}

// ---------------- layer-0: fused CSR mean-gather + conv + stats partials ----------------
// 128 threads, 32 nodes/block. Threads 0-31 gather mean6, 64-127 load root x.
__global__ void k_layer0(const float* __restrict__ x,
                         const float* __restrict__ wl, const float* __restrict__ bl,
                         const float* __restrict__ wr) {
    __shared__ float sIn[32 * 12];   // per node: [mean6 | x6]
    int n0 = blockIdx.x * 32;
    int tid = threadIdx.x;

    float wlr[IN_DIM], wrr[IN_DIM];
#pragma unroll
    for (int k = 0; k < IN_DIM; k++) {
        wlr[k] = __ldg(&wl[tid * IN_DIM + k]);
        wrr[k] = __ldg(&wr[tid * IN_DIM + k]);
    }
    float bias = __ldg(&bl[tid]);

    if (tid < 32) {
        int n = n0 + tid;
        float a[IN_DIM] = {0.f, 0.f, 0.f, 0.f, 0.f, 0.f};
        if (n < N_NODES) {
            int beg = g_off[n], end = g_off[n + 1];
            for (int j = beg; j < end; j++) {
                int s = g_esrc[j];
                const float2* xs = (const float2*)(x + s * IN_DIM);  // 24B row, 8B aligned
                float2 v0 = __ldg(xs), v1 = __ldg(xs + 1), v2 = __ldg(xs + 2);
                a[0] += v0.x; a[1] += v0.y; a[2] += v1.x;
                a[3] += v1.y; a[4] += v2.x; a[5] += v2.y;
            }
            float iv = g_inv[n];
#pragma unroll
            for (int k = 0; k < IN_DIM; k++) a[k] *= iv;
        }
#pragma unroll
        for (int k = 0; k < IN_DIM; k++) sIn[tid * 12 + k] = a[k];
    } else if (tid >= 64 && tid < 128) {
        int i = (tid - 64) * 3;          // 3 values each, covers 192 = 32 nodes x 6
#pragma unroll
        for (int q = 0; q < 3; q++, i++) {
            int nl = i / 6, f = i % 6;
            int n = n0 + nl;
            sIn[nl * 12 + 6 + f] = (n < N_NODES) ? x[n * IN_DIM + f] : 0.0f;
        }
    }
    __syncthreads();

    float s = 0.0f, s2 = 0.0f;
    for (int i = 0; i < 32; i++) {
        int n = n0 + i;
        if (n >= N_NODES) break;
        const float* in = &sIn[i * 12];
        float h = bias;
#pragma unroll
        for (int k = 0; k < IN_DIM; k++) h += wlr[k] * in[k] + wrr[k] * in[6 + k];
        g_h0[(size_t)n * HID + tid] = __float2half_rn(h);
        s += h; s2 += h * h;
    }
    g_p0[blockIdx.x * HID + tid] = make_float2(s, s2);   // plain store, no atomics
}

// ---------------- stats reduction: 32 blocks, 32-long atomic chains ----------------
__global__ void k_reduce0() {
    int c = threadIdx.x;
    float s = 0.0f, q = 0.0f;
    for (int b = blockIdx.x; b < L0_BLOCKS; b += 32) {
        float2 v = g_p0[b * HID + c];
        s += v.x; q += v.y;
    }
    atomicAdd(&g_sum0[c], s);
    atomicAdd(&g_sq0[c], q);
}

__global__ void k_reduce1() {
    int c = threadIdx.x;
    float s = 0.0f, q = 0.0f;
    for (int b = blockIdx.x; b < GM_BLOCKS * 2; b += 32) {
        float2 v = g_p1[b * HID + c];
        s += v.x; q += v.y;
    }
    atomicAdd(&g_sum1[c], s);
    atomicAdd(&g_sq1[c], q);
}

// ---------------- layer-1 fused: CSR gather-mean + GEMM (tf32 mma.sync) ----------------
__device__ __forceinline__ uint32_t f2tf32(float f) {
    uint32_t u;
    asm("cvt.rna.tf32.f32 %0, %1;" : "=r"(u) : "f"(f));
    return u;
}

__device__ __forceinline__ void mma_tf32(float& c0, float& c1, float& c2, float& c3,
                                         uint32_t a0, uint32_t a1, uint32_t a2, uint32_t a3,
                                         uint32_t b0, uint32_t b1) {
    asm volatile(
        "mma.sync.aligned.m16n8k8.row.col.f32.tf32.tf32.f32 "
        "{%0,%1,%2,%3}, {%4,%5,%6,%7}, {%8,%9}, {%0,%1,%2,%3};"
        : "+f"(c0), "+f"(c1), "+f"(c2), "+f"(c3)
        : "r"(a0), "r"(a1), "r"(a2), "r"(a3), "r"(b0), "r"(b1));
}

// unpack 4 halves (uint2) -> float4
__device__ __forceinline__ float4 h4_to_f4(uint2 u) {
    __half2 p01 = *(__half2*)&u.x;
    __half2 p23 = *(__half2*)&u.y;
    float2 f01 = __half22float2(p01);
    float2 f23 = __half22float2(p23);
    return make_float4(f01.x, f01.y, f23.x, f23.y);
}

#define AFSTR 132  // full-width A tile row stride; 132 % 32 == 4 -> frag loads conflict-free
#define WSTR  20   // W tile (k=16) row stride; verified conflict-free fragment reads

__global__ void __launch_bounds__(256) k_gemm1f(const float* __restrict__ wl,
                                                const float* __restrict__ bl,
                                                const float* __restrict__ wr,
                                                const float* __restrict__ g0,
                                                const float* __restrict__ b0) {
    __shared__ float As[64 * AFSTR];   // 33.8 KB — full 64x128 A tile (tf32 bits)
    __shared__ float Ws[128 * WSTR];   // 10.2 KB — 128x16 W tile
    __shared__ float sScale[HID], sShift[HID];

    int tid  = threadIdx.x;
    int n0   = blockIdx.x * 64;
    int warp = tid >> 5, lane = tid & 31;
    int wm = (warp & 1) * 32;          // warp m-offset (0/32)
    int wn = (warp >> 1) * 32;         // warp n-offset (0/32/64/96)
    int gi = lane >> 2, ti = lane & 3;

    if (tid < HID) {
        float sc, sh;
        bn_affine(g_sum0[tid], g_sq0[tid], __ldg(&g0[tid]), __ldg(&b0[tid]), sc, sh);
        sScale[tid] = sc; sShift[tid] = sh;
    }
    __syncthreads();

    // ---- gather phase: neighbor-mean of BN0+ReLU(h0 fp16) straight into As (tf32) ----
    {
        float4 sc = *(const float4*)&sScale[lane * 4];
        float4 sh = *(const float4*)&sShift[lane * 4];
        int rbase = warp * 8;
#pragma unroll 1
        for (int r = 0; r < 8; r++) {
            int n = n0 + rbase + r;
            float4 acc = make_float4(0.f, 0.f, 0.f, 0.f);
            if (n < N_NODES) {
                int beg = __ldg(&g_off[n]), end = __ldg(&g_off[n + 1]);
                for (int j = beg; j < end; j++) {
                    int s = __ldg(&g_esrc[j]);     // broadcast
                    uint2 u = ((const uint2*)(g_h0 + (size_t)s * HID))[lane];  // 4 halves
                    float4 v = h4_to_f4(u);
                    acc.x += fmaxf(fmaf(v.x, sc.x, sh.x), 0.0f);
                    acc.y += fmaxf(fmaf(v.y, sc.y, sh.y), 0.0f);
                    acc.z += fmaxf(fmaf(v.z, sc.z, sh.z), 0.0f);
                    acc.w += fmaxf(fmaf(v.w, sc.w, sh.w), 0.0f);
                }
                float iv = __ldg(&g_inv[n]);
                acc.x *= iv; acc.y *= iv; acc.z *= iv; acc.w *= iv;
            }
            float* dst = &As[(rbase + r) * AFSTR + lane * 4];
            dst[0] = __uint_as_float(f2tf32(acc.x));
            dst[1] = __uint_as_float(f2tf32(acc.y));
            dst[2] = __uint_as_float(f2tf32(acc.z));
            dst[3] = __uint_as_float(f2tf32(acc.w));
        }
    }
    __syncthreads();

    float c[2][4][4];
#pragma unroll
    for (int i = 0; i < 2; i++)
#pragma unroll
        for (int j = 0; j < 4; j++)
#pragma unroll
            for (int q = 0; q < 4; q++) c[i][j][q] = 0.0f;

    int wc = tid >> 1, wk = (tid & 1) * 8;   // W staging: row, k8 chunk

#pragma unroll 1
    for (int p = 0; p < 2; p++) {
        const float* W = p ? wr : wl;
        if (p == 1) {
            // restage As with BN0+ReLU(h0 fp16) for the root term
            int r = tid >> 2;
            int anode = n0 + r;
#pragma unroll
            for (int j = 0; j < 8; j++) {
                int col = (tid & 3) * 4 + j * 16;
                float4 v = make_float4(0.f, 0.f, 0.f, 0.f);
                if (anode < N_NODES)
                    v = h4_to_f4(*(const uint2*)(g_h0 + (size_t)anode * HID + col));
                float4 sc = *(const float4*)&sScale[col];
                float4 sh = *(const float4*)&sShift[col];
                v.x = fmaxf(fmaf(v.x, sc.x, sh.x), 0.0f);
                v.y = fmaxf(fmaf(v.y, sc.y, sh.y), 0.0f);
                v.z = fmaxf(fmaf(v.z, sc.z, sh.z), 0.0f);
                v.w = fmaxf(fmaf(v.w, sc.w, sh.w), 0.0f);
                float* dst = &As[r * AFSTR + col];
                dst[0] = __uint_as_float(f2tf32(v.x));
                dst[1] = __uint_as_float(f2tf32(v.y));
                dst[2] = __uint_as_float(f2tf32(v.z));
                dst[3] = __uint_as_float(f2tf32(v.w));
            }
        }
#pragma unroll 1
        for (int kt = 0; kt < HID; kt += 16) {
            // stage W 128x16
            {
                const float4* wp = (const float4*)(W + wc * HID + kt + wk);
                float4 w0 = __ldg(wp), w1 = __ldg(wp + 1);
                float4 t0, t1;
                t0.x = __uint_as_float(f2tf32(w0.x));
                t0.y = __uint_as_float(f2tf32(w0.y));
                t0.z = __uint_as_float(f2tf32(w0.z));
                t0.w = __uint_as_float(f2tf32(w0.w));
                t1.x = __uint_as_float(f2tf32(w1.x));
                t1.y = __uint_as_float(f2tf32(w1.y));
                t1.z = __uint_as_float(f2tf32(w1.z));
                t1.w = __uint_as_float(f2tf32(w1.w));
                *(float4*)&Ws[wc * WSTR + wk]     = t0;
                *(float4*)&Ws[wc * WSTR + wk + 4] = t1;
            }
            __syncthreads();

#pragma unroll
            for (int kk2 = 0; kk2 < 16; kk2 += 8) {
                int kcol = kt + kk2;
                uint32_t a[2][4], b[4][2];
#pragma unroll
                for (int i = 0; i < 2; i++) {
                    int mb = wm + i * 16;
                    a[i][0] = __float_as_uint(As[(mb + gi)     * AFSTR + kcol + ti]);
                    a[i][1] = __float_as_uint(As[(mb + 8 + gi) * AFSTR + kcol + ti]);
                    a[i][2] = __float_as_uint(As[(mb + gi)     * AFSTR + kcol + 4 + ti]);
                    a[i][3] = __float_as_uint(As[(mb + 8 + gi) * AFSTR + kcol + 4 + ti]);
                }
#pragma unroll
                for (int j = 0; j < 4; j++) {
                    int nb = wn + j * 8;
                    b[j][0] = __float_as_uint(Ws[(nb + gi) * WSTR + kk2 + ti]);
                    b[j][1] = __float_as_uint(Ws[(nb + gi) * WSTR + kk2 + 4 + ti]);
                }
#pragma unroll
                for (int i = 0; i < 2; i++)
#pragma unroll
                    for (int j = 0; j < 4; j++)
                        mma_tf32(c[i][j][0], c[i][j][1], c[i][j][2], c[i][j][3],
                                 a[i][0], a[i][1], a[i][2], a[i][3],
                                 b[j][0], b[j][1]);
            }
            __syncthreads();   // protect next stage (W and/or As overwrite)
        }
    }

    // epilogue: + bias, store fp16 h1, per-warp stats partials (fp32, no atomics)
    float ssum[4][2], ssq[4][2];
#pragma unroll
    for (int j = 0; j < 4; j++) { ssum[j][0] = ssum[j][1] = 0.f; ssq[j][0] = ssq[j][1] = 0.f; }

#pragma unroll
    for (int i = 0; i < 2; i++) {
#pragma unroll
        for (int j = 0; j < 4; j++) {
            int ch = wn + j * 8 + ti * 2;
            float b0v = __ldg(&bl[ch]), b1v = __ldg(&bl[ch + 1]);
            int nodeA = n0 + wm + i * 16 + gi;
            int nodeB = nodeA + 8;
            if (nodeA < N_NODES) {
                float o0 = c[i][j][0] + b0v, o1 = c[i][j][1] + b1v;
                *(__half2*)(g_h1 + (size_t)nodeA * HID + ch) = __floats2half2_rn(o0, o1);
                ssum[j][0] += o0; ssq[j][0] += o0 * o0;
                ssum[j][1] += o1; ssq[j][1] += o1 * o1;
            }
            if (nodeB < N_NODES) {
                float o2 = c[i][j][2] + b0v, o3 = c[i][j][3] + b1v;
                *(__half2*)(g_h1 + (size_t)nodeB * HID + ch) = __floats2half2_rn(o2, o3);
                ssum[j][0] += o2; ssq[j][0] += o2 * o2;
                ssum[j][1] += o3; ssq[j][1] += o3 * o3;
            }
        }
    }
    int slot = blockIdx.x * 2 + (warp & 1);
#pragma unroll
    for (int j = 0; j < 4; j++) {
#pragma unroll
        for (int h = 0; h < 2; h++) {
            float a = ssum[j][h], b = ssq[j][h];
#pragma unroll
            for (int o = 4; o < 32; o <<= 1) {
                a += __shfl_xor_sync(0xffffffffu, a, o);
                b += __shfl_xor_sync(0xffffffffu, b, o);
            }
            if (gi == 0) {
                int ch = wn + j * 8 + ti * 2 + h;
                g_p1[slot * HID + ch] = make_float2(a, b);
            }
        }
    }
}

// ---------------- layer-2: BN1+ReLU on load (inline affine), project ----------------
__global__ void k_proj2(const float* __restrict__ wl2, const float* __restrict__ wr2,
                        const float* __restrict__ g1, const float* __restrict__ b1) {
    int gt = blockIdx.x * blockDim.x + threadIdx.x;
    int n = gt >> 5;
    if (n >= N_NODES) return;
    int lane = threadIdx.x & 31;
    float4 s4 = ((const float4*)g_sum1)[lane];
    float4 q4 = ((const float4*)g_sq1)[lane];
    float4 gm = __ldg((const float4*)g1 + lane);
    float4 bt = __ldg((const float4*)b1 + lane);
    float4 sc, sh;
    bn_affine(s4.x, q4.x, gm.x, bt.x, sc.x, sh.x);
    bn_affine(s4.y, q4.y, gm.y, bt.y, sc.y, sh.y);
    bn_affine(s4.z, q4.z, gm.z, bt.z, sc.z, sh.z);
    bn_affine(s4.w, q4.w, gm.w, bt.w, sc.w, sh.w);

    float4 h = h4_to_f4(((const uint2*)(g_h1 + (size_t)n * HID))[lane]);
    h.x = fmaxf(fmaf(h.x, sc.x, sh.x), 0.0f);
    h.y = fmaxf(fmaf(h.y, sc.y, sh.y), 0.0f);
    h.z = fmaxf(fmaf(h.z, sc.z, sh.z), 0.0f);
    h.w = fmaxf(fmaf(h.w, sc.w, sh.w), 0.0f);
    float4 a = __ldg((const float4*)wl2 + lane);
    float4 b = __ldg((const float4*)wr2 + lane);
    float pl = h.x * a.x + h.y * a.y + h.z * a.z + h.w * a.w;
    float pr = h.x * b.x + h.y * b.y + h.z * b.z + h.w * b.w;
#pragma unroll
    for (int o = 16; o > 0; o >>= 1) {
        pl += __shfl_xor_sync(0xffffffffu, pl, o);
        pr += __shfl_xor_sync(0xffffffffu, pr, o);
    }
    if (lane == 0) { g_pl[n] = pl; g_pr[n] = pr; }
}

__global__ void k_final(const float* __restrict__ bl2, float* __restrict__ out) {
    int n = blockIdx.x * blockDim.x + threadIdx.x;
    if (n >= N_NODES) return;
    int beg = g_off[n], end = g_off[n + 1];
    float a = 0.0f;
    for (int j = beg; j < end; j++) a += g_pl[g_esrc[j]];
    float z = a * g_inv[n] + __ldg(bl2) + g_pr[n];
    out[n] = 1.0f / (1.0f + expf(-z));
}

// ---------------- launch: kernel launches ONLY (11 launches) ----------------
extern "C" void kernel_launch(void* const* d_in, const int* in_sizes, int n_in,
                              void* d_out, int out_size) {
    const float* x   = (const float*)d_in[0];
    const int*   ei  = (const int*)d_in[1];   // int32 (JAX x64-disabled demotes int64)
    const float* wl0 = (const float*)d_in[2];
    const float* bl0 = (const float*)d_in[3];
    const float* wr0 = (const float*)d_in[4];
    const float* g0  = (const float*)d_in[5];
    const float* b0  = (const float*)d_in[6];
    const float* wl1 = (const float*)d_in[7];
    const float* bl1 = (const float*)d_in[8];
    const float* wr1 = (const float*)d_in[9];
    const float* g1  = (const float*)d_in[10];
    const float* b1  = (const float*)d_in[11];
    const float* wl2 = (const float*)d_in[12];
    const float* bl2 = (const float*)d_in[13];
    const float* wr2 = (const float*)d_in[14];
    float* out = (float*)d_out;

    k_zero  <<<512, 256>>>();
    k_count <<<(N_EDGES + 255) / 256, 256>>>(ei);
    k_scan1 <<<SCAN_NB, SCAN_B>>>();
    k_scan3i<<<SCAN_NB, SCAN_B>>>();
    k_fill  <<<(N_EDGES + 255) / 256, 256>>>(ei);

    k_layer0 <<<L0_BLOCKS, 128>>>(x, wl0, bl0, wr0);
    k_reduce0<<<32, 128>>>();

    k_gemm1f <<<GM_BLOCKS, 256>>>(wl1, bl1, wr1, g0, b0);
    k_reduce1<<<32, 128>>>();

    k_proj2<<<(N_NODES * 32 + 255) / 256, 256>>>(wl2, wr2, g1, b1);
    k_final<<<(N_NODES + 255) / 256, 256>>>(bl2, out);
}